// round 2
// baseline (speedup 1.0000x reference)
#include <cuda_runtime.h>
#include <math.h>

#define BATCH  16
#define NSEQ   1024
#define DMODEL 256
#define HEADS  8
#define DKDIM  32
#define NUMREL 3969

typedef unsigned long long ull;

// Scratch (allocation-free rule: __device__ globals)
__device__ float g_q[BATCH * HEADS * NSEQ * DKDIM];
__device__ float g_k[BATCH * HEADS * NSEQ * DKDIM];
__device__ float g_v[BATCH * HEADS * NSEQ * DKDIM];
__device__ float g_o[BATCH * NSEQ * DMODEL];

// ---------------- packed f32x2 helpers (sm_103a FFMA2 path) ----------------
__device__ __forceinline__ ull ffma2(ull a, ull b, ull c) {
    ull d;
    asm("fma.rn.f32x2 %0, %1, %2, %3;" : "=l"(d) : "l"(a), "l"(b), "l"(c));
    return d;
}
__device__ __forceinline__ ull fmul2(ull a, ull b) {
    ull d;
    asm("mul.rn.f32x2 %0, %1, %2;" : "=l"(d) : "l"(a), "l"(b));
    return d;
}
__device__ __forceinline__ ull pack2(float lo, float hi) {
    ull r;
    asm("mov.b64 %0, {%1, %2};" : "=l"(r) : "f"(lo), "f"(hi));
    return r;
}
__device__ __forceinline__ ull dup2(float x) { return pack2(x, x); }
__device__ __forceinline__ void unpack2(ull v, float& lo, float& hi) {
    asm("mov.b64 {%0, %1}, %2;" : "=f"(lo), "=f"(hi) : "l"(v));
}

// ---------------------------------------------------------------------------
// GEMM core: C_tile = A_tile @ W_tile^T, 64x64 tile, BK=16, 256 threads,
// 4x4 register tile computed as FFMA2 row-pairs.
// As/Ws stored transposed [k][m] with stride 68 (16B-aligned rows).
// ---------------------------------------------------------------------------
__device__ __forceinline__ void gemm_core(
    const float* __restrict__ A, const float* __restrict__ W,
    int m0, int n0, int tid, float p[4][4])
{
    __shared__ float As[16 * 68];
    __shared__ float Ws[16 * 68];

    int ty = tid >> 4, tx = tid & 15;
    int lr = tid >> 2;          // 0..63
    int lc = (tid & 3) << 2;    // 0,4,8,12
    const float* Ap = A + (size_t)(m0 + lr) * DMODEL + lc;
    const float* Wp = W + (size_t)(n0 + lr) * DMODEL + lc;

    ull acc2[2][4] = {{0ull,0ull,0ull,0ull},{0ull,0ull,0ull,0ull}};

    for (int k0 = 0; k0 < DMODEL; k0 += 16) {
        float4 a = *(const float4*)(Ap + k0);
        float4 w = *(const float4*)(Wp + k0);
        __syncthreads();
        As[(lc + 0) * 68 + lr] = a.x; As[(lc + 1) * 68 + lr] = a.y;
        As[(lc + 2) * 68 + lr] = a.z; As[(lc + 3) * 68 + lr] = a.w;
        Ws[(lc + 0) * 68 + lr] = w.x; Ws[(lc + 1) * 68 + lr] = w.y;
        Ws[(lc + 2) * 68 + lr] = w.z; Ws[(lc + 3) * 68 + lr] = w.w;
        __syncthreads();
#pragma unroll
        for (int kk = 0; kk < 16; kk++) {
            ulonglong2 av = *(const ulonglong2*)&As[kk * 68 + 4 * ty];
            float4 wv = *(const float4*)&Ws[kk * 68 + 4 * tx];
            ull w0 = dup2(wv.x), w1 = dup2(wv.y), w2 = dup2(wv.z), w3 = dup2(wv.w);
            acc2[0][0] = ffma2(av.x, w0, acc2[0][0]);
            acc2[1][0] = ffma2(av.y, w0, acc2[1][0]);
            acc2[0][1] = ffma2(av.x, w1, acc2[0][1]);
            acc2[1][1] = ffma2(av.y, w1, acc2[1][1]);
            acc2[0][2] = ffma2(av.x, w2, acc2[0][2]);
            acc2[1][2] = ffma2(av.y, w2, acc2[1][2]);
            acc2[0][3] = ffma2(av.x, w3, acc2[0][3]);
            acc2[1][3] = ffma2(av.y, w3, acc2[1][3]);
        }
    }
#pragma unroll
    for (int j = 0; j < 4; j++) {
        unpack2(acc2[0][j], p[0][j], p[1][j]);
        unpack2(acc2[1][j], p[2][j], p[3][j]);
    }
}

__global__ __launch_bounds__(256) void proj_qkv_kernel(
    const float* __restrict__ A, const float* __restrict__ W,
    const float* __restrict__ bias, int which)
{
    float p[4][4];
    int tid = threadIdx.x;
    int m0 = blockIdx.y * 64, n0 = blockIdx.x * 64;
    gemm_core(A, W, m0, n0, tid, p);

    int ty = tid >> 4, tx = tid & 15;
    float* dst = (which == 0) ? g_q : (which == 1) ? g_k : g_v;
#pragma unroll
    for (int i = 0; i < 4; i++) {
        int m = m0 + 4 * ty + i;
        int b = m >> 10, n = m & 1023;
#pragma unroll
        for (int j = 0; j < 4; j++) {
            int c = n0 + 4 * tx + j;
            int h = c >> 5, d = c & 31;
            dst[(((size_t)(b * HEADS + h)) * NSEQ + n) * DKDIM + d] =
                p[i][j] + bias[c];
        }
    }
}

__global__ __launch_bounds__(256) void out_proj_kernel(
    const float* __restrict__ W, const float* __restrict__ bias,
    float* __restrict__ C)
{
    float p[4][4];
    int tid = threadIdx.x;
    int m0 = blockIdx.y * 64, n0 = blockIdx.x * 64;
    gemm_core(g_o, W, m0, n0, tid, p);

    int ty = tid >> 4, tx = tid & 15;
#pragma unroll
    for (int i = 0; i < 4; i++) {
        int m = m0 + 4 * ty + i;
#pragma unroll
        for (int j = 0; j < 4; j++) {
            int c = n0 + 4 * tx + j;
            C[(size_t)m * DMODEL + c] = p[i][j] + bias[c];
        }
    }
}

// ---------------------------------------------------------------------------
// Fused flash attention with arithmetic relative-position bias, FFMA2 math.
// Block: 64 query rows of one (b,h). 16x16 threads, 4q x 4k per thread (QK),
// 4q x 2c per thread (PV).
//
// SMEM (exactly 48KB static):
//   Qt[32][64]  : Q transposed [d][row], col index swizzled r^((d&15)<<2)
//   Kt[32][64]  : same for K
//   Vdup[64][64]: V duplicated [kk][2c],[2c+1]=V[kk][c], cols swizzled by kk
//   Pt[64][64]  : P transposed [kk][row], cols swizzled row^(4*(kk>>2))
// ---------------------------------------------------------------------------
__global__ __launch_bounds__(256) void attn_kernel(
    const float* __restrict__ bias_table)
{
    __shared__ float Qt[32 * 64];
    __shared__ float Kt[32 * 64];
    __shared__ float Vdup[64 * 64];
    __shared__ float Pt[64 * 64];

    const float SCALE = 0.17677669529663687f;  // 1/sqrt(32)

    int bh = blockIdx.y;             // 0..127
    int h = bh & (HEADS - 1);
    int b = bh >> 3;
    int qbase = blockIdx.x * 64;
    int tid = threadIdx.x;
    int ty = tid >> 4, tx = tid & 15;

    const float* qptr = g_q + (size_t)bh * NSEQ * DKDIM;
    const float* kptr = g_k + (size_t)bh * NSEQ * DKDIM;
    const float* vptr = g_v + (size_t)bh * NSEQ * DKDIM;
    const float* brow = bias_table + h * NUMREL;

    int r = tid >> 2;           // 0..63
    int d0 = (tid & 3) << 3;    // 0,8,16,24

    // ---- stage Q tile transposed + swizzled (once) ----
    {
        const float* src = qptr + (size_t)(qbase + r) * DKDIM + d0;
        float4 a0 = *(const float4*)src;
        float4 a1 = *(const float4*)(src + 4);
        float qv[8] = {a0.x, a0.y, a0.z, a0.w, a1.x, a1.y, a1.z, a1.w};
#pragma unroll
        for (int m = 0; m < 8; m++) {
            int d = d0 + m;
            Qt[d * 64 + (r ^ ((d & 15) << 2))] = qv[m];
        }
    }

    // rowcode for arithmetic rel_index: idx = rowcode[i] - colcode[j]
    int rowcode[4];
#pragma unroll
    for (int i = 0; i < 4; i++) {
        int qrow = qbase + 4 * ty + i;
        rowcode[i] = (qrow >> 5) * 63 + (qrow & 31) + 1984;  // +31*63+31
    }

    float mrow[4], lrow[4];
    ull o00 = 0, o01 = 0, o10 = 0, o11 = 0;  // [row-pair][col]
#pragma unroll
    for (int i = 0; i < 4; i++) { mrow[i] = -1e30f; lrow[i] = 0.f; }

    for (int kb = 0; kb < NSEQ; kb += 64) {
        // ---- stage K (transposed+swizzled) and Vdup ----
        const float* ks = kptr + (size_t)(kb + r) * DKDIM + d0;
        const float* vs = vptr + (size_t)(kb + r) * DKDIM + d0;
        float4 k0 = *(const float4*)ks;
        float4 k1 = *(const float4*)(ks + 4);
        float4 w0 = *(const float4*)vs;
        float4 w1 = *(const float4*)(vs + 4);
        __syncthreads();  // previous tile's PV readers done
        {
            float kv[8] = {k0.x, k0.y, k0.z, k0.w, k1.x, k1.y, k1.z, k1.w};
#pragma unroll
            for (int m = 0; m < 8; m++) {
                int d = d0 + m;
                Kt[d * 64 + (r ^ ((d & 15) << 2))] = kv[m];
            }
            int vsw = (r & 15) << 2;
            *(float4*)&Vdup[r * 64 + ((2 * d0 + 0) ^ vsw)] =
                make_float4(w0.x, w0.x, w0.y, w0.y);
            *(float4*)&Vdup[r * 64 + ((2 * d0 + 4) ^ vsw)] =
                make_float4(w0.z, w0.z, w0.w, w0.w);
            *(float4*)&Vdup[r * 64 + ((2 * d0 + 8) ^ vsw)] =
                make_float4(w1.x, w1.x, w1.y, w1.y);
            *(float4*)&Vdup[r * 64 + ((2 * d0 + 12) ^ vsw)] =
                make_float4(w1.z, w1.z, w1.w, w1.w);
        }
        __syncthreads();

        // ---- S = Q K^T via FFMA2 (rows packed in pairs) ----
        ull acc2[2][4] = {{0ull,0ull,0ull,0ull},{0ull,0ull,0ull,0ull}};
#pragma unroll 8
        for (int d = 0; d < DKDIM; d++) {
            int sw = (d & 15) << 2;
            ulonglong2 av = *(const ulonglong2*)&Qt[d * 64 + ((4 * ty) ^ sw)];
            float4 bv = *(const float4*)&Kt[d * 64 + ((4 * tx) ^ sw)];
            ull b0 = dup2(bv.x), b1 = dup2(bv.y), b2 = dup2(bv.z), b3 = dup2(bv.w);
            acc2[0][0] = ffma2(av.x, b0, acc2[0][0]);
            acc2[1][0] = ffma2(av.y, b0, acc2[1][0]);
            acc2[0][1] = ffma2(av.x, b1, acc2[0][1]);
            acc2[1][1] = ffma2(av.y, b1, acc2[1][1]);
            acc2[0][2] = ffma2(av.x, b2, acc2[0][2]);
            acc2[1][2] = ffma2(av.y, b2, acc2[1][2]);
            acc2[0][3] = ffma2(av.x, b3, acc2[0][3]);
            acc2[1][3] = ffma2(av.y, b3, acc2[1][3]);
        }

        float p[4][4];
#pragma unroll
        for (int j = 0; j < 4; j++) {
            unpack2(acc2[0][j], p[0][j], p[1][j]);
            unpack2(acc2[1][j], p[2][j], p[3][j]);
        }

        // ---- scale + relative-position bias (arithmetic index) ----
        int kc = kb + 4 * tx;
        int cc[4];
#pragma unroll
        for (int j = 0; j < 4; j++) {
            int kcol = kc + j;
            cc[j] = (kcol >> 5) * 63 + (kcol & 31);
        }
        float fac[4];
#pragma unroll
        for (int i = 0; i < 4; i++) {
#pragma unroll
            for (int j = 0; j < 4; j++)
                p[i][j] = fmaf(p[i][j], SCALE, __ldg(brow + (rowcode[i] - cc[j])));

            float tmax = fmaxf(fmaxf(p[i][0], p[i][1]), fmaxf(p[i][2], p[i][3]));
            tmax = fmaxf(tmax, __shfl_xor_sync(0xffffffffu, tmax, 1));
            tmax = fmaxf(tmax, __shfl_xor_sync(0xffffffffu, tmax, 2));
            tmax = fmaxf(tmax, __shfl_xor_sync(0xffffffffu, tmax, 4));
            tmax = fmaxf(tmax, __shfl_xor_sync(0xffffffffu, tmax, 8));
            float mnew = fmaxf(mrow[i], tmax);
            fac[i] = __expf(mrow[i] - mnew);
            mrow[i] = mnew;
            float rs = 0.f;
#pragma unroll
            for (int j = 0; j < 4; j++) {
                p[i][j] = __expf(p[i][j] - mnew);
                rs += p[i][j];
            }
            rs += __shfl_xor_sync(0xffffffffu, rs, 1);
            rs += __shfl_xor_sync(0xffffffffu, rs, 2);
            rs += __shfl_xor_sync(0xffffffffu, rs, 4);
            rs += __shfl_xor_sync(0xffffffffu, rs, 8);
            lrow[i] = lrow[i] * fac[i] + rs;
        }

        // rescale O accumulators (packed row-pairs)
        ull f2a = pack2(fac[0], fac[1]);
        ull f2b = pack2(fac[2], fac[3]);
        o00 = fmul2(o00, f2a); o01 = fmul2(o01, f2a);
        o10 = fmul2(o10, f2b); o11 = fmul2(o11, f2b);

        // ---- write P transposed [kk][row], swizzled ----
#pragma unroll
        for (int j = 0; j < 4; j++) {
            int kk = 4 * tx + j;
            *(float4*)&Pt[kk * 64 + ((4 * ty) ^ ((kk >> 2) << 2))] =
                make_float4(p[0][j], p[1][j], p[2][j], p[3][j]);
        }
        __syncthreads();

        // ---- O += P @ V : per kk 2x LDS.128 + 4 FFMA2 ----
#pragma unroll 8
        for (int kk = 0; kk < 64; kk++) {
            int s = (kk >> 2) << 2;
            ulonglong2 pr = *(const ulonglong2*)&Pt[kk * 64 + ((4 * ty) ^ s)];
            ulonglong2 vv = *(const ulonglong2*)&Vdup[kk * 64 + ((4 * tx) ^ ((kk & 15) << 2))];
            o00 = ffma2(pr.x, vv.x, o00);
            o01 = ffma2(pr.x, vv.y, o01);
            o10 = ffma2(pr.y, vv.x, o10);
            o11 = ffma2(pr.y, vv.y, o11);
        }
    }

    // ---- normalize + write O in [B, N, H*dk] layout ----
    float o[4][2];
    unpack2(o00, o[0][0], o[1][0]);
    unpack2(o01, o[0][1], o[1][1]);
    unpack2(o10, o[2][0], o[3][0]);
    unpack2(o11, o[2][1], o[3][1]);
#pragma unroll
    for (int i = 0; i < 4; i++) {
        float inv = 1.0f / lrow[i];
        int qrow = qbase + 4 * ty + i;
        float2 o2 = make_float2(o[i][0] * inv, o[i][1] * inv);
        *(float2*)(g_o + ((size_t)(b * NSEQ + qrow)) * DMODEL + h * DKDIM + 2 * tx) = o2;
    }
}

// ---------------------------------------------------------------------------
extern "C" void kernel_launch(void* const* d_in, const int* in_sizes, int n_in,
                              void* d_out, int out_size)
{
    const float* x          = (const float*)d_in[0];
    const float* Wq         = (const float*)d_in[1];
    const float* bq         = (const float*)d_in[2];
    const float* Wk         = (const float*)d_in[3];
    const float* bk         = (const float*)d_in[4];
    const float* Wv         = (const float*)d_in[5];
    const float* bv         = (const float*)d_in[6];
    const float* Wo         = (const float*)d_in[7];
    const float* bo         = (const float*)d_in[8];
    const float* bias_table = (const float*)d_in[9];
    float* out = (float*)d_out;

    dim3 gthr(256);
    dim3 ggrid(DMODEL / 64, (BATCH * NSEQ) / 64);   // (4, 256)

    proj_qkv_kernel<<<ggrid, gthr>>>(x, Wq, bq, 0);
    proj_qkv_kernel<<<ggrid, gthr>>>(x, Wk, bk, 1);
    proj_qkv_kernel<<<ggrid, gthr>>>(x, Wv, bv, 2);

    attn_kernel<<<dim3(NSEQ / 64, BATCH * HEADS), 256>>>(bias_table);

    out_proj_kernel<<<ggrid, gthr>>>(Wo, bo, out);
}

// round 3
// speedup vs baseline: 2.7286x; 2.7286x over previous
#include <cuda_runtime.h>
#include <math.h>

#define BATCH  16
#define NSEQ   1024
#define DMODEL 256
#define HEADS  8
#define DKDIM  32
#define NUMREL 3969

// Scratch (allocation-free rule: __device__ globals)
__device__ float g_q[BATCH * HEADS * NSEQ * DKDIM];
__device__ float g_k[BATCH * HEADS * NSEQ * DKDIM];
__device__ float g_v[BATCH * HEADS * NSEQ * DKDIM];
__device__ float g_o[BATCH * NSEQ * DMODEL];

// ----------------------- tf32 mma helpers ---------------------------------
__device__ __forceinline__ unsigned f2tf(float f) {
    unsigned u;
    asm("cvt.rna.tf32.f32 %0, %1;" : "=r"(u) : "f"(f));
    return u;
}

// D(16x8,f32) += A(16x8,tf32) * B(8x8,tf32)
__device__ __forceinline__ void mma8(float4& d, const unsigned* a,
                                     unsigned b0, unsigned b1) {
    asm volatile(
        "mma.sync.aligned.m16n8k8.row.col.f32.tf32.tf32.f32 "
        "{%0,%1,%2,%3},{%4,%5,%6,%7},{%8,%9},{%0,%1,%2,%3};"
        : "+f"(d.x), "+f"(d.y), "+f"(d.z), "+f"(d.w)
        : "r"(a[0]), "r"(a[1]), "r"(a[2]), "r"(a[3]), "r"(b0), "r"(b1));
}

// ---------------------------------------------------------------------------
// GEMM: C = A @ W^T (+bias in epilogue). Out tile 128(M) x 64(N), 256 thr,
// 8 warps; warp w owns rows 16w..16w+15 (8 n-tiles of 8). BK=32.
// W row-major IS the col-major B operand of mma (B[k][n] = W[n][k]).
// SMEM staged pre-converted to tf32. Strides: As 36 (bank 4g+t), Ws 36.
// ---------------------------------------------------------------------------
__device__ __forceinline__ void gemm_mma_core(
    const float* __restrict__ A, const float* __restrict__ W,
    int m0, int n0, float4 cf[8])
{
    __shared__ unsigned As[128 * 36];
    __shared__ unsigned Ws[64 * 36];

    int tid = threadIdx.x;
    int w = tid >> 5, lane = tid & 31;
    int g = lane >> 2, t = lane & 3;

#pragma unroll
    for (int j = 0; j < 8; j++) cf[j] = make_float4(0.f, 0.f, 0.f, 0.f);

    int ar = tid >> 1, ac = (tid & 1) << 4;   // A: 128 rows x 32, 16 f/thread
    int wr = tid >> 2, wc = (tid & 3) << 3;   // W: 64 rows x 32, 8 f/thread

    for (int k0 = 0; k0 < DMODEL; k0 += 32) {
        const float* ap = A + (size_t)(m0 + ar) * DMODEL + k0 + ac;
        const float* wp = W + (size_t)(n0 + wr) * DMODEL + k0 + wc;
        float4 a0 = *(const float4*)(ap + 0);
        float4 a1 = *(const float4*)(ap + 4);
        float4 a2 = *(const float4*)(ap + 8);
        float4 a3 = *(const float4*)(ap + 12);
        float4 w0 = *(const float4*)(wp + 0);
        float4 w1 = *(const float4*)(wp + 4);
        __syncthreads();
        {
            uint4 u;
            u.x = f2tf(a0.x); u.y = f2tf(a0.y); u.z = f2tf(a0.z); u.w = f2tf(a0.w);
            *(uint4*)&As[ar * 36 + ac + 0] = u;
            u.x = f2tf(a1.x); u.y = f2tf(a1.y); u.z = f2tf(a1.z); u.w = f2tf(a1.w);
            *(uint4*)&As[ar * 36 + ac + 4] = u;
            u.x = f2tf(a2.x); u.y = f2tf(a2.y); u.z = f2tf(a2.z); u.w = f2tf(a2.w);
            *(uint4*)&As[ar * 36 + ac + 8] = u;
            u.x = f2tf(a3.x); u.y = f2tf(a3.y); u.z = f2tf(a3.z); u.w = f2tf(a3.w);
            *(uint4*)&As[ar * 36 + ac + 12] = u;
            u.x = f2tf(w0.x); u.y = f2tf(w0.y); u.z = f2tf(w0.z); u.w = f2tf(w0.w);
            *(uint4*)&Ws[wr * 36 + wc + 0] = u;
            u.x = f2tf(w1.x); u.y = f2tf(w1.y); u.z = f2tf(w1.z); u.w = f2tf(w1.w);
            *(uint4*)&Ws[wr * 36 + wc + 4] = u;
        }
        __syncthreads();

#pragma unroll
        for (int ks = 0; ks < 4; ks++) {
            unsigned aa[4];
            aa[0] = As[(16 * w + g) * 36 + 8 * ks + t];
            aa[1] = As[(16 * w + g + 8) * 36 + 8 * ks + t];
            aa[2] = As[(16 * w + g) * 36 + 8 * ks + t + 4];
            aa[3] = As[(16 * w + g + 8) * 36 + 8 * ks + t + 4];
#pragma unroll
            for (int j = 0; j < 8; j++) {
                unsigned b0 = Ws[(8 * j + g) * 36 + 8 * ks + t];
                unsigned b1 = Ws[(8 * j + g) * 36 + 8 * ks + t + 4];
                mma8(cf[j], aa, b0, b1);
            }
        }
    }
}

__global__ __launch_bounds__(256) void proj_qkv_kernel(
    const float* __restrict__ A, const float* __restrict__ W,
    const float* __restrict__ bias, int which)
{
    float4 cf[8];
    int m0 = blockIdx.y * 128, n0 = blockIdx.x * 64;
    gemm_mma_core(A, W, m0, n0, cf);

    int tid = threadIdx.x;
    int w = tid >> 5, lane = tid & 31;
    int g = lane >> 2, t = lane & 3;
    float* dst = (which == 0) ? g_q : (which == 1) ? g_k : g_v;

    int m_a = m0 + 16 * w + g;
    int m_b = m_a + 8;
#pragma unroll
    for (int j = 0; j < 8; j++) {
        int c = n0 + 8 * j + 2 * t;          // even, c&31 <= 30
        int h = c >> 5, d = c & 31;
        float b0 = __ldg(bias + c), b1 = __ldg(bias + c + 1);
        {
            int b = m_a >> 10, n = m_a & 1023;
            float* p = dst + (((size_t)(b * HEADS + h)) * NSEQ + n) * DKDIM + d;
            p[0] = cf[j].x + b0; p[1] = cf[j].y + b1;
        }
        {
            int b = m_b >> 10, n = m_b & 1023;
            float* p = dst + (((size_t)(b * HEADS + h)) * NSEQ + n) * DKDIM + d;
            p[0] = cf[j].z + b0; p[1] = cf[j].w + b1;
        }
    }
}

__global__ __launch_bounds__(256) void out_proj_kernel(
    const float* __restrict__ W, const float* __restrict__ bias,
    float* __restrict__ C)
{
    float4 cf[8];
    int m0 = blockIdx.y * 128, n0 = blockIdx.x * 64;
    gemm_mma_core(g_o, W, m0, n0, cf);

    int tid = threadIdx.x;
    int w = tid >> 5, lane = tid & 31;
    int g = lane >> 2, t = lane & 3;
    int m_a = m0 + 16 * w + g;
#pragma unroll
    for (int j = 0; j < 8; j++) {
        int c = n0 + 8 * j + 2 * t;
        float b0 = __ldg(bias + c), b1 = __ldg(bias + c + 1);
        *(float2*)(C + (size_t)m_a * DMODEL + c) =
            make_float2(cf[j].x + b0, cf[j].y + b1);
        *(float2*)(C + (size_t)(m_a + 8) * DMODEL + c) =
            make_float2(cf[j].z + b0, cf[j].w + b1);
    }
}

// ---------------------------------------------------------------------------
// Fused flash attention, tf32 mma, arithmetic relative-position bias.
// Block: 128 threads (4 warps), 64 query rows of one (b,h); warp w owns
// q-rows 16w..16w+15. Key tiles of 64. Q fragments persist in registers.
// SMEM strides: Ks 36 (bank 4g+t), Vs 40 (8t+g), Ps 68 (4g+t) -- all 32
// lanes of every fragment load hit distinct banks.
// ---------------------------------------------------------------------------
__global__ __launch_bounds__(128) void attn_kernel(
    const float* __restrict__ bias_table)
{
    __shared__ unsigned Ks[64 * 36];   //  9216 B
    __shared__ unsigned Vs[64 * 40];   // 10240 B
    __shared__ unsigned Ps[64 * 68];   // 17408 B   (total 36864 B)

    const float SCALE = 0.17677669529663687f;  // 1/sqrt(32)

    int bh = blockIdx.y;                 // 0..127
    int h = bh & (HEADS - 1);
    int b = bh >> 3;
    int qbase = blockIdx.x * 64;
    int tid = threadIdx.x;
    int w = tid >> 5, lane = tid & 31;
    int g = lane >> 2, t = lane & 3;

    const float* qptr = g_q + (size_t)bh * NSEQ * DKDIM;
    const float* kptr = g_k + (size_t)bh * NSEQ * DKDIM;
    const float* vptr = g_v + (size_t)bh * NSEQ * DKDIM;
    const float* brow = bias_table + h * NUMREL;

    // --- Q fragments (persist across all key tiles) ---
    unsigned qa[4][4];
    {
        const float* q0 = qptr + (size_t)(qbase + 16 * w + g) * DKDIM;
        const float* q1 = q0 + 8 * DKDIM;
#pragma unroll
        for (int ks = 0; ks < 4; ks++) {
            qa[ks][0] = f2tf(__ldg(q0 + 8 * ks + t));
            qa[ks][1] = f2tf(__ldg(q1 + 8 * ks + t));
            qa[ks][2] = f2tf(__ldg(q0 + 8 * ks + t + 4));
            qa[ks][3] = f2tf(__ldg(q1 + 8 * ks + t + 4));
        }
    }

    // arithmetic rel-index rowcodes: idx = rowcode - colcode
    int qr0 = qbase + 16 * w + g;
    int qr1 = qr0 + 8;
    int rc0 = (qr0 >> 5) * 63 + (qr0 & 31) + 1984;
    int rc1 = (qr1 >> 5) * 63 + (qr1 & 31) + 1984;

    float m0 = -1e30f, m1 = -1e30f, l0 = 0.f, l1 = 0.f;
    float4 of[4];
#pragma unroll
    for (int jj = 0; jj < 4; jj++) of[jj] = make_float4(0.f, 0.f, 0.f, 0.f);

    int sr = tid >> 1;            // staging row 0..63
    int sq = (tid & 1) << 4;      // staging col 0 / 16

    for (int kb = 0; kb < NSEQ; kb += 64) {
        // ---- stage K,V (converted to tf32) ----
        const float* ksrc = kptr + (size_t)(kb + sr) * DKDIM + sq;
        const float* vsrc = vptr + (size_t)(kb + sr) * DKDIM + sq;
        float4 k0 = *(const float4*)(ksrc + 0);
        float4 k1 = *(const float4*)(ksrc + 4);
        float4 k2 = *(const float4*)(ksrc + 8);
        float4 k3 = *(const float4*)(ksrc + 12);
        float4 v0 = *(const float4*)(vsrc + 0);
        float4 v1 = *(const float4*)(vsrc + 4);
        float4 v2 = *(const float4*)(vsrc + 8);
        float4 v3 = *(const float4*)(vsrc + 12);
        __syncthreads();   // prior tile's mma reads of Ks/Vs complete
        {
            uint4 u;
            u.x = f2tf(k0.x); u.y = f2tf(k0.y); u.z = f2tf(k0.z); u.w = f2tf(k0.w);
            *(uint4*)&Ks[sr * 36 + sq + 0] = u;
            u.x = f2tf(k1.x); u.y = f2tf(k1.y); u.z = f2tf(k1.z); u.w = f2tf(k1.w);
            *(uint4*)&Ks[sr * 36 + sq + 4] = u;
            u.x = f2tf(k2.x); u.y = f2tf(k2.y); u.z = f2tf(k2.z); u.w = f2tf(k2.w);
            *(uint4*)&Ks[sr * 36 + sq + 8] = u;
            u.x = f2tf(k3.x); u.y = f2tf(k3.y); u.z = f2tf(k3.z); u.w = f2tf(k3.w);
            *(uint4*)&Ks[sr * 36 + sq + 12] = u;
            u.x = f2tf(v0.x); u.y = f2tf(v0.y); u.z = f2tf(v0.z); u.w = f2tf(v0.w);
            *(uint4*)&Vs[sr * 40 + sq + 0] = u;
            u.x = f2tf(v1.x); u.y = f2tf(v1.y); u.z = f2tf(v1.z); u.w = f2tf(v1.w);
            *(uint4*)&Vs[sr * 40 + sq + 4] = u;
            u.x = f2tf(v2.x); u.y = f2tf(v2.y); u.z = f2tf(v2.z); u.w = f2tf(v2.w);
            *(uint4*)&Vs[sr * 40 + sq + 8] = u;
            u.x = f2tf(v3.x); u.y = f2tf(v3.y); u.z = f2tf(v3.z); u.w = f2tf(v3.w);
            *(uint4*)&Vs[sr * 40 + sq + 12] = u;
        }
        __syncthreads();

        // ---- S = Q K^T : 8 n-tiles x 4 k-steps of m16n8k8 ----
        float4 sf[8];
#pragma unroll
        for (int j = 0; j < 8; j++) sf[j] = make_float4(0.f, 0.f, 0.f, 0.f);
#pragma unroll
        for (int ks = 0; ks < 4; ks++) {
#pragma unroll
            for (int j = 0; j < 8; j++) {
                unsigned b0 = Ks[(8 * j + g) * 36 + 8 * ks + t];
                unsigned b1 = Ks[(8 * j + g) * 36 + 8 * ks + t + 4];
                mma8(sf[j], qa[ks], b0, b1);
            }
        }

        // ---- bias + online softmax on fragments ----
        float mx0 = -1e30f, mx1 = -1e30f;
#pragma unroll
        for (int j = 0; j < 8; j++) {
            int kcol = kb + 8 * j + 2 * t;
            int cA = (kcol >> 5) * 63 + (kcol & 31);
            int cB = ((kcol + 1) >> 5) * 63 + ((kcol + 1) & 31);
            sf[j].x = fmaf(sf[j].x, SCALE, __ldg(brow + (rc0 - cA)));
            sf[j].y = fmaf(sf[j].y, SCALE, __ldg(brow + (rc0 - cB)));
            sf[j].z = fmaf(sf[j].z, SCALE, __ldg(brow + (rc1 - cA)));
            sf[j].w = fmaf(sf[j].w, SCALE, __ldg(brow + (rc1 - cB)));
            mx0 = fmaxf(mx0, fmaxf(sf[j].x, sf[j].y));
            mx1 = fmaxf(mx1, fmaxf(sf[j].z, sf[j].w));
        }
        mx0 = fmaxf(mx0, __shfl_xor_sync(0xffffffffu, mx0, 1));
        mx0 = fmaxf(mx0, __shfl_xor_sync(0xffffffffu, mx0, 2));
        mx1 = fmaxf(mx1, __shfl_xor_sync(0xffffffffu, mx1, 1));
        mx1 = fmaxf(mx1, __shfl_xor_sync(0xffffffffu, mx1, 2));

        float nm0 = fmaxf(m0, mx0), nm1 = fmaxf(m1, mx1);
        float fac0 = __expf(m0 - nm0), fac1 = __expf(m1 - nm1);
        m0 = nm0; m1 = nm1;

        float s0 = 0.f, s1 = 0.f;
#pragma unroll
        for (int j = 0; j < 8; j++) {
            sf[j].x = __expf(sf[j].x - nm0);
            sf[j].y = __expf(sf[j].y - nm0);
            sf[j].z = __expf(sf[j].z - nm1);
            sf[j].w = __expf(sf[j].w - nm1);
            s0 += sf[j].x + sf[j].y;
            s1 += sf[j].z + sf[j].w;
            uint2 p0; p0.x = f2tf(sf[j].x); p0.y = f2tf(sf[j].y);
            uint2 p1; p1.x = f2tf(sf[j].z); p1.y = f2tf(sf[j].w);
            *(uint2*)&Ps[(16 * w + g) * 68 + 8 * j + 2 * t] = p0;
            *(uint2*)&Ps[(16 * w + g + 8) * 68 + 8 * j + 2 * t] = p1;
        }
        s0 += __shfl_xor_sync(0xffffffffu, s0, 1);
        s0 += __shfl_xor_sync(0xffffffffu, s0, 2);
        s1 += __shfl_xor_sync(0xffffffffu, s1, 1);
        s1 += __shfl_xor_sync(0xffffffffu, s1, 2);
        l0 = l0 * fac0 + s0;
        l1 = l1 * fac1 + s1;

#pragma unroll
        for (int jj = 0; jj < 4; jj++) {
            of[jj].x *= fac0; of[jj].y *= fac0;
            of[jj].z *= fac1; of[jj].w *= fac1;
        }
        __syncwarp();   // P rows of this warp visible to this warp's lanes

        // ---- O += P @ V : 4 n-tiles x 8 k-steps ----
#pragma unroll
        for (int ks = 0; ks < 8; ks++) {
            unsigned pa[4];
            pa[0] = Ps[(16 * w + g) * 68 + 8 * ks + t];
            pa[1] = Ps[(16 * w + g + 8) * 68 + 8 * ks + t];
            pa[2] = Ps[(16 * w + g) * 68 + 8 * ks + t + 4];
            pa[3] = Ps[(16 * w + g + 8) * 68 + 8 * ks + t + 4];
#pragma unroll
            for (int jj = 0; jj < 4; jj++) {
                unsigned b0 = Vs[(8 * ks + t) * 40 + 8 * jj + g];
                unsigned b1 = Vs[(8 * ks + t + 4) * 40 + 8 * jj + g];
                mma8(of[jj], pa, b0, b1);
            }
        }
    }

    // ---- normalize + write O in [B, N, H*dk] layout ----
    float inv0 = 1.0f / l0, inv1 = 1.0f / l1;
#pragma unroll
    for (int jj = 0; jj < 4; jj++) {
        int col = h * DKDIM + 8 * jj + 2 * t;
        *(float2*)(g_o + ((size_t)b * NSEQ + qr0) * DMODEL + col) =
            make_float2(of[jj].x * inv0, of[jj].y * inv0);
        *(float2*)(g_o + ((size_t)b * NSEQ + qr1) * DMODEL + col) =
            make_float2(of[jj].z * inv1, of[jj].w * inv1);
    }
}

// ---------------------------------------------------------------------------
extern "C" void kernel_launch(void* const* d_in, const int* in_sizes, int n_in,
                              void* d_out, int out_size)
{
    const float* x          = (const float*)d_in[0];
    const float* Wq         = (const float*)d_in[1];
    const float* bq         = (const float*)d_in[2];
    const float* Wk         = (const float*)d_in[3];
    const float* bk         = (const float*)d_in[4];
    const float* Wv         = (const float*)d_in[5];
    const float* bv         = (const float*)d_in[6];
    const float* Wo         = (const float*)d_in[7];
    const float* bo         = (const float*)d_in[8];
    const float* bias_table = (const float*)d_in[9];
    float* out = (float*)d_out;

    dim3 ggrid(DMODEL / 64, (BATCH * NSEQ) / 128);   // (4, 128)

    proj_qkv_kernel<<<ggrid, 256>>>(x, Wq, bq, 0);
    proj_qkv_kernel<<<ggrid, 256>>>(x, Wk, bk, 1);
    proj_qkv_kernel<<<ggrid, 256>>>(x, Wv, bv, 2);

    attn_kernel<<<dim3(NSEQ / 64, BATCH * HEADS), 128>>>(bias_table);

    out_proj_kernel<<<ggrid, 256>>>(Wo, bo, out);
}

// round 4
// speedup vs baseline: 2.9321x; 1.0746x over previous
#include <cuda_runtime.h>
#include <math.h>

#define BATCH  16
#define NSEQ   1024
#define DMODEL 256
#define HEADS  8
#define DKDIM  32
#define NUMREL 3969

// Scratch (allocation-free rule: __device__ globals)
__device__ float g_q[BATCH * HEADS * NSEQ * DKDIM];
__device__ float g_k[BATCH * HEADS * NSEQ * DKDIM];
__device__ float g_v[BATCH * HEADS * NSEQ * DKDIM];
__device__ float g_o[BATCH * NSEQ * DMODEL];

// ----------------------- tf32 mma helpers ---------------------------------
__device__ __forceinline__ unsigned f2tf(float f) {
    unsigned u;
    asm("cvt.rna.tf32.f32 %0, %1;" : "=r"(u) : "f"(f));
    return u;
}

// D(16x8,f32) += A(16x8,tf32) * B(8x8,tf32)
__device__ __forceinline__ void mma8(float4& d, const unsigned* a,
                                     unsigned b0, unsigned b1) {
    asm volatile(
        "mma.sync.aligned.m16n8k8.row.col.f32.tf32.tf32.f32 "
        "{%0,%1,%2,%3},{%4,%5,%6,%7},{%8,%9},{%0,%1,%2,%3};"
        : "+f"(d.x), "+f"(d.y), "+f"(d.z), "+f"(d.w)
        : "r"(a[0]), "r"(a[1]), "r"(a[2]), "r"(a[3]), "r"(b0), "r"(b1));
}

// ---------------------------------------------------------------------------
// GEMM core: C = A @ W^T. Out tile 256(M) x 64(N), 256 thr, 8 warps;
// warp w owns rows 32w..32w+31 (two 16-row A fragments -> each B fragment
// load feeds 2 MMAs). BK=32. SMEM staged pre-converted to tf32, stride 36.
// ---------------------------------------------------------------------------
__device__ __forceinline__ void gemm_mma_core(
    const float* __restrict__ A, const float* __restrict__ W,
    int m0, int n0, float4 cf[2][8])
{
    __shared__ unsigned As[256 * 36];   // 36864 B
    __shared__ unsigned Ws[64 * 36];    //  9216 B

    int tid = threadIdx.x;
    int w = tid >> 5, lane = tid & 31;
    int g = lane >> 2, t = lane & 3;

#pragma unroll
    for (int f = 0; f < 2; f++)
#pragma unroll
        for (int j = 0; j < 8; j++) cf[f][j] = make_float4(0.f, 0.f, 0.f, 0.f);

    int wr = tid >> 2, wc = (tid & 3) << 3;   // W: 64 rows x 32, 8 f/thread

    for (int k0 = 0; k0 < DMODEL; k0 += 32) {
        const float* ap = A + (size_t)(m0 + tid) * DMODEL + k0;  // 1 row/thread
        const float* wp = W + (size_t)(n0 + wr) * DMODEL + k0 + wc;
        float4 a[8];
#pragma unroll
        for (int i = 0; i < 8; i++) a[i] = *(const float4*)(ap + 4 * i);
        float4 w0 = *(const float4*)(wp + 0);
        float4 w1 = *(const float4*)(wp + 4);
        __syncthreads();
#pragma unroll
        for (int i = 0; i < 8; i++) {
            uint4 u;
            u.x = f2tf(a[i].x); u.y = f2tf(a[i].y);
            u.z = f2tf(a[i].z); u.w = f2tf(a[i].w);
            *(uint4*)&As[tid * 36 + 4 * i] = u;
        }
        {
            uint4 u;
            u.x = f2tf(w0.x); u.y = f2tf(w0.y); u.z = f2tf(w0.z); u.w = f2tf(w0.w);
            *(uint4*)&Ws[wr * 36 + wc + 0] = u;
            u.x = f2tf(w1.x); u.y = f2tf(w1.y); u.z = f2tf(w1.z); u.w = f2tf(w1.w);
            *(uint4*)&Ws[wr * 36 + wc + 4] = u;
        }
        __syncthreads();

#pragma unroll
        for (int ks = 0; ks < 4; ks++) {
            unsigned aa[8];
            int rbase = (32 * w + g) * 36 + 8 * ks + t;
            aa[0] = As[rbase];
            aa[1] = As[rbase + 8 * 36];
            aa[2] = As[rbase + 4];
            aa[3] = As[rbase + 8 * 36 + 4];
            aa[4] = As[rbase + 16 * 36];
            aa[5] = As[rbase + 24 * 36];
            aa[6] = As[rbase + 16 * 36 + 4];
            aa[7] = As[rbase + 24 * 36 + 4];
#pragma unroll
            for (int j = 0; j < 8; j++) {
                unsigned b0 = Ws[(8 * j + g) * 36 + 8 * ks + t];
                unsigned b1 = Ws[(8 * j + g) * 36 + 8 * ks + t + 4];
                mma8(cf[0][j], aa, b0, b1);
                mma8(cf[1][j], aa + 4, b0, b1);
            }
        }
    }
}

// Fused Q/K/V projection: blockIdx.z selects which weight/bias/destination.
__global__ __launch_bounds__(256) void proj_qkv_kernel(
    const float* __restrict__ A,
    const float* __restrict__ Wq, const float* __restrict__ bq,
    const float* __restrict__ Wk, const float* __restrict__ bk,
    const float* __restrict__ Wv, const float* __restrict__ bv)
{
    int which = blockIdx.z;
    const float* W    = (which == 0) ? Wq : (which == 1) ? Wk : Wv;
    const float* bias = (which == 0) ? bq : (which == 1) ? bk : bv;
    float* dst        = (which == 0) ? g_q : (which == 1) ? g_k : g_v;

    float4 cf[2][8];
    int m0 = blockIdx.y * 256, n0 = blockIdx.x * 64;
    gemm_mma_core(A, W, m0, n0, cf);

    int tid = threadIdx.x;
    int w = tid >> 5, lane = tid & 31;
    int g = lane >> 2, t = lane & 3;

#pragma unroll
    for (int f = 0; f < 2; f++) {
        int m_a = m0 + 32 * w + g + 16 * f;
        int m_b = m_a + 8;
#pragma unroll
        for (int j = 0; j < 8; j++) {
            int c = n0 + 8 * j + 2 * t;          // even, c&31 <= 30
            int h = c >> 5, d = c & 31;
            float b0 = __ldg(bias + c), b1 = __ldg(bias + c + 1);
            {
                int b = m_a >> 10, n = m_a & 1023;
                float* p = dst + (((size_t)(b * HEADS + h)) * NSEQ + n) * DKDIM + d;
                p[0] = cf[f][j].x + b0; p[1] = cf[f][j].y + b1;
            }
            {
                int b = m_b >> 10, n = m_b & 1023;
                float* p = dst + (((size_t)(b * HEADS + h)) * NSEQ + n) * DKDIM + d;
                p[0] = cf[f][j].z + b0; p[1] = cf[f][j].w + b1;
            }
        }
    }
}

__global__ __launch_bounds__(256) void out_proj_kernel(
    const float* __restrict__ W, const float* __restrict__ bias,
    float* __restrict__ C)
{
    float4 cf[2][8];
    int m0 = blockIdx.y * 256, n0 = blockIdx.x * 64;
    gemm_mma_core(g_o, W, m0, n0, cf);

    int tid = threadIdx.x;
    int w = tid >> 5, lane = tid & 31;
    int g = lane >> 2, t = lane & 3;
#pragma unroll
    for (int f = 0; f < 2; f++) {
        int m_a = m0 + 32 * w + g + 16 * f;
#pragma unroll
        for (int j = 0; j < 8; j++) {
            int c = n0 + 8 * j + 2 * t;
            float b0 = __ldg(bias + c), b1 = __ldg(bias + c + 1);
            *(float2*)(C + (size_t)m_a * DMODEL + c) =
                make_float2(cf[f][j].x + b0, cf[f][j].y + b1);
            *(float2*)(C + (size_t)(m_a + 8) * DMODEL + c) =
                make_float2(cf[f][j].z + b0, cf[f][j].w + b1);
        }
    }
}

// ---------------------------------------------------------------------------
// Fused flash attention, tf32 mma, arithmetic relative-position bias.
// Block: 128 threads (4 warps), 128 query rows; warp w owns q-rows
// 32w..32w+31 (two A fragments -> every K/V/P B-fragment feeds 2 MMAs).
// Key tiles of 64. Q fragments persist in registers.
// SMEM strides: Ks 36 (bank 4g+t), Vs 40 (8t+g), Ps 68 (4g+t).
// Dynamic SMEM: (64*36 + 64*40 + 128*68)*4 = 54272 B.
// ---------------------------------------------------------------------------
#define ATTN_SMEM_WORDS (64 * 36 + 64 * 40 + 128 * 68)

__global__ __launch_bounds__(128) void attn_kernel(
    const float* __restrict__ bias_table)
{
    extern __shared__ unsigned sm_u[];
    unsigned* Ks = sm_u;                       // 64*36
    unsigned* Vs = sm_u + 64 * 36;             // 64*40
    unsigned* Ps = sm_u + 64 * 36 + 64 * 40;   // 128*68

    const float SCALE = 0.17677669529663687f;  // 1/sqrt(32)

    int bh = blockIdx.y;                 // 0..127
    int h = bh & (HEADS - 1);
    int b = bh >> 3;
    int qbase = blockIdx.x * 128;
    int tid = threadIdx.x;
    int w = tid >> 5, lane = tid & 31;
    int g = lane >> 2, t = lane & 3;

    const float* qptr = g_q + (size_t)bh * NSEQ * DKDIM;
    const float* kptr = g_k + (size_t)bh * NSEQ * DKDIM;
    const float* vptr = g_v + (size_t)bh * NSEQ * DKDIM;
    const float* brow = bias_table + h * NUMREL;

    int r0 = qbase + 32 * w + g;   // warp's first fragment row

    // --- Q fragments (persist): frag f covers rows r0+16f, r0+16f+8 ---
    unsigned qa[4][8];
#pragma unroll
    for (int f = 0; f < 2; f++) {
        const float* qA = qptr + (size_t)(r0 + 16 * f) * DKDIM;
        const float* qB = qA + 8 * DKDIM;
#pragma unroll
        for (int ks = 0; ks < 4; ks++) {
            qa[ks][4 * f + 0] = f2tf(__ldg(qA + 8 * ks + t));
            qa[ks][4 * f + 1] = f2tf(__ldg(qB + 8 * ks + t));
            qa[ks][4 * f + 2] = f2tf(__ldg(qA + 8 * ks + t + 4));
            qa[ks][4 * f + 3] = f2tf(__ldg(qB + 8 * ks + t + 4));
        }
    }

    // rowcodes for arithmetic rel-index (rows r0, r0+8, r0+16, r0+24)
    int rc[4];
#pragma unroll
    for (int i = 0; i < 4; i++) {
        int qr = r0 + 8 * i;
        rc[i] = (qr >> 5) * 63 + (qr & 31) + 1984;
    }

    float m[4], l[4];
    float4 of[2][4];
#pragma unroll
    for (int i = 0; i < 4; i++) { m[i] = -1e30f; l[i] = 0.f; }
#pragma unroll
    for (int f = 0; f < 2; f++)
#pragma unroll
        for (int jj = 0; jj < 4; jj++) of[f][jj] = make_float4(0.f, 0.f, 0.f, 0.f);

    int sr = tid >> 1;            // staging row 0..63
    int sq = (tid & 1) << 4;      // staging col 0 / 16

    for (int kb = 0; kb < NSEQ; kb += 64) {
        // ---- stage K,V (converted to tf32) ----
        const float* ksrc = kptr + (size_t)(kb + sr) * DKDIM + sq;
        const float* vsrc = vptr + (size_t)(kb + sr) * DKDIM + sq;
        float4 kr[4], vr[4];
#pragma unroll
        for (int i = 0; i < 4; i++) {
            kr[i] = *(const float4*)(ksrc + 4 * i);
            vr[i] = *(const float4*)(vsrc + 4 * i);
        }
        __syncthreads();   // prior tile's mma reads of Ks/Vs complete
#pragma unroll
        for (int i = 0; i < 4; i++) {
            uint4 u;
            u.x = f2tf(kr[i].x); u.y = f2tf(kr[i].y);
            u.z = f2tf(kr[i].z); u.w = f2tf(kr[i].w);
            *(uint4*)&Ks[sr * 36 + sq + 4 * i] = u;
            u.x = f2tf(vr[i].x); u.y = f2tf(vr[i].y);
            u.z = f2tf(vr[i].z); u.w = f2tf(vr[i].w);
            *(uint4*)&Vs[sr * 40 + sq + 4 * i] = u;
        }
        __syncthreads();

        // ---- S = Q K^T : 8 n-tiles x 4 k-steps, 2 M-frags per B load ----
        float4 sf[2][8];
#pragma unroll
        for (int f = 0; f < 2; f++)
#pragma unroll
            for (int j = 0; j < 8; j++) sf[f][j] = make_float4(0.f, 0.f, 0.f, 0.f);
#pragma unroll
        for (int ks = 0; ks < 4; ks++) {
#pragma unroll
            for (int j = 0; j < 8; j++) {
                unsigned b0 = Ks[(8 * j + g) * 36 + 8 * ks + t];
                unsigned b1 = Ks[(8 * j + g) * 36 + 8 * ks + t + 4];
                mma8(sf[0][j], &qa[ks][0], b0, b1);
                mma8(sf[1][j], &qa[ks][4], b0, b1);
            }
        }

        // ---- bias + online softmax on fragments ----
        float mx[4] = {-1e30f, -1e30f, -1e30f, -1e30f};
#pragma unroll
        for (int f = 0; f < 2; f++) {
#pragma unroll
            for (int j = 0; j < 8; j++) {
                int kcol = kb + 8 * j + 2 * t;
                int cA = (kcol >> 5) * 63 + (kcol & 31);
                int cB = ((kcol + 1) >> 5) * 63 + ((kcol + 1) & 31);
                sf[f][j].x = fmaf(sf[f][j].x, SCALE, __ldg(brow + (rc[2 * f] - cA)));
                sf[f][j].y = fmaf(sf[f][j].y, SCALE, __ldg(brow + (rc[2 * f] - cB)));
                sf[f][j].z = fmaf(sf[f][j].z, SCALE, __ldg(brow + (rc[2 * f + 1] - cA)));
                sf[f][j].w = fmaf(sf[f][j].w, SCALE, __ldg(brow + (rc[2 * f + 1] - cB)));
                mx[2 * f]     = fmaxf(mx[2 * f],     fmaxf(sf[f][j].x, sf[f][j].y));
                mx[2 * f + 1] = fmaxf(mx[2 * f + 1], fmaxf(sf[f][j].z, sf[f][j].w));
            }
        }
        float fac[4], s[4];
#pragma unroll
        for (int i = 0; i < 4; i++) {
            mx[i] = fmaxf(mx[i], __shfl_xor_sync(0xffffffffu, mx[i], 1));
            mx[i] = fmaxf(mx[i], __shfl_xor_sync(0xffffffffu, mx[i], 2));
            float nm = fmaxf(m[i], mx[i]);
            fac[i] = __expf(m[i] - nm);
            m[i] = nm;
            s[i] = 0.f;
        }
#pragma unroll
        for (int f = 0; f < 2; f++) {
#pragma unroll
            for (int j = 0; j < 8; j++) {
                sf[f][j].x = __expf(sf[f][j].x - m[2 * f]);
                sf[f][j].y = __expf(sf[f][j].y - m[2 * f]);
                sf[f][j].z = __expf(sf[f][j].z - m[2 * f + 1]);
                sf[f][j].w = __expf(sf[f][j].w - m[2 * f + 1]);
                s[2 * f]     += sf[f][j].x + sf[f][j].y;
                s[2 * f + 1] += sf[f][j].z + sf[f][j].w;
                uint2 p0; p0.x = f2tf(sf[f][j].x); p0.y = f2tf(sf[f][j].y);
                uint2 p1; p1.x = f2tf(sf[f][j].z); p1.y = f2tf(sf[f][j].w);
                *(uint2*)&Ps[(32 * w + g + 16 * f) * 68 + 8 * j + 2 * t] = p0;
                *(uint2*)&Ps[(32 * w + g + 16 * f + 8) * 68 + 8 * j + 2 * t] = p1;
            }
        }
#pragma unroll
        for (int i = 0; i < 4; i++) {
            s[i] += __shfl_xor_sync(0xffffffffu, s[i], 1);
            s[i] += __shfl_xor_sync(0xffffffffu, s[i], 2);
            l[i] = l[i] * fac[i] + s[i];
        }
#pragma unroll
        for (int f = 0; f < 2; f++)
#pragma unroll
            for (int jj = 0; jj < 4; jj++) {
                of[f][jj].x *= fac[2 * f];     of[f][jj].y *= fac[2 * f];
                of[f][jj].z *= fac[2 * f + 1]; of[f][jj].w *= fac[2 * f + 1];
            }
        __syncwarp();   // warp's own P rows visible

        // ---- O += P @ V : 4 n-tiles x 8 k-steps, 2 M-frags per B load ----
#pragma unroll
        for (int ks = 0; ks < 8; ks++) {
            unsigned pa[8];
            int pbase = (32 * w + g) * 68 + 8 * ks + t;
            pa[0] = Ps[pbase];
            pa[1] = Ps[pbase + 8 * 68];
            pa[2] = Ps[pbase + 4];
            pa[3] = Ps[pbase + 8 * 68 + 4];
            pa[4] = Ps[pbase + 16 * 68];
            pa[5] = Ps[pbase + 24 * 68];
            pa[6] = Ps[pbase + 16 * 68 + 4];
            pa[7] = Ps[pbase + 24 * 68 + 4];
#pragma unroll
            for (int jj = 0; jj < 4; jj++) {
                unsigned b0 = Vs[(8 * ks + t) * 40 + 8 * jj + g];
                unsigned b1 = Vs[(8 * ks + t + 4) * 40 + 8 * jj + g];
                mma8(of[0][jj], pa, b0, b1);
                mma8(of[1][jj], pa + 4, b0, b1);
            }
        }
    }

    // ---- normalize + write O in [B, N, H*dk] layout ----
#pragma unroll
    for (int f = 0; f < 2; f++) {
        float inv0 = 1.0f / l[2 * f], inv1 = 1.0f / l[2 * f + 1];
        int qrA = r0 + 16 * f, qrB = qrA + 8;
#pragma unroll
        for (int jj = 0; jj < 4; jj++) {
            int col = h * DKDIM + 8 * jj + 2 * t;
            *(float2*)(g_o + ((size_t)b * NSEQ + qrA) * DMODEL + col) =
                make_float2(of[f][jj].x * inv0, of[f][jj].y * inv0);
            *(float2*)(g_o + ((size_t)b * NSEQ + qrB) * DMODEL + col) =
                make_float2(of[f][jj].z * inv1, of[f][jj].w * inv1);
        }
    }
}

// ---------------------------------------------------------------------------
extern "C" void kernel_launch(void* const* d_in, const int* in_sizes, int n_in,
                              void* d_out, int out_size)
{
    const float* x          = (const float*)d_in[0];
    const float* Wq         = (const float*)d_in[1];
    const float* bq         = (const float*)d_in[2];
    const float* Wk         = (const float*)d_in[3];
    const float* bk         = (const float*)d_in[4];
    const float* Wv         = (const float*)d_in[5];
    const float* bv         = (const float*)d_in[6];
    const float* Wo         = (const float*)d_in[7];
    const float* bo         = (const float*)d_in[8];
    const float* bias_table = (const float*)d_in[9];
    float* out = (float*)d_out;

    cudaFuncSetAttribute(attn_kernel,
                         cudaFuncAttributeMaxDynamicSharedMemorySize,
                         ATTN_SMEM_WORDS * 4);

    dim3 pgrid(DMODEL / 64, (BATCH * NSEQ) / 256, 3);   // (4, 64, 3)
    proj_qkv_kernel<<<pgrid, 256>>>(x, Wq, bq, Wk, bk, Wv, bv);

    attn_kernel<<<dim3(NSEQ / 128, BATCH * HEADS), 128,
                  ATTN_SMEM_WORDS * 4>>>(bias_table);

    dim3 ogrid(DMODEL / 64, (BATCH * NSEQ) / 256);      // (4, 64)
    out_proj_kernel<<<ogrid, 256>>>(Wo, bo, out);
}

// round 5
// speedup vs baseline: 4.0219x; 1.3717x over previous
#include <cuda_runtime.h>
#include <math.h>

#define BATCH  16
#define NSEQ   1024
#define DMODEL 256
#define HEADS  8
#define DKDIM  32
#define NUMREL 3969

// Scratch (allocation-free rule: __device__ globals)
__device__ float g_q[BATCH * HEADS * NSEQ * DKDIM];
__device__ float g_k[BATCH * HEADS * NSEQ * DKDIM];
__device__ float g_v[BATCH * HEADS * NSEQ * DKDIM];
__device__ float g_o[BATCH * NSEQ * DMODEL];

// ----------------------- tf32 mma helpers ---------------------------------
__device__ __forceinline__ unsigned f2tf(float f) {
    unsigned u;
    asm("cvt.rna.tf32.f32 %0, %1;" : "=r"(u) : "f"(f));
    return u;
}
__device__ __forceinline__ uint4 cvt4(float4 a) {
    uint4 u;
    u.x = f2tf(a.x); u.y = f2tf(a.y); u.z = f2tf(a.z); u.w = f2tf(a.w);
    return u;
}

// D(16x8,f32) += A(16x8,tf32) * B(8x8,tf32)
__device__ __forceinline__ void mma8(float4& d, const unsigned* a,
                                     unsigned b0, unsigned b1) {
    asm volatile(
        "mma.sync.aligned.m16n8k8.row.col.f32.tf32.tf32.f32 "
        "{%0,%1,%2,%3},{%4,%5,%6,%7},{%8,%9},{%0,%1,%2,%3};"
        : "+f"(d.x), "+f"(d.y), "+f"(d.z), "+f"(d.w)
        : "r"(a[0]), "r"(a[1]), "r"(a[2]), "r"(a[3]), "r"(b0), "r"(b1));
}

// ---------------------------------------------------------------------------
// GEMM core: C = A @ W^T. Out tile 256(M) x 64(N), 256 thr, 8 warps;
// warp w owns rows 32w..32w+31 (two 16-row A fragments -> each B fragment
// load feeds 2 MMAs). BK=32. SMEM staged pre-converted to tf32, stride 36.
// Global loads coalesced: 8 threads cover one 128B row -> 4 lines/LDG.128.
// ---------------------------------------------------------------------------
__device__ __forceinline__ void gemm_mma_core(
    const float* __restrict__ A, const float* __restrict__ W,
    int m0, int n0, float4 cf[2][8])
{
    __shared__ unsigned As[256 * 36];   // 36864 B
    __shared__ unsigned Ws[64 * 36];    //  9216 B

    int tid = threadIdx.x;
    int w = tid >> 5, lane = tid & 31;
    int g = lane >> 2, t = lane & 3;

#pragma unroll
    for (int f = 0; f < 2; f++)
#pragma unroll
        for (int j = 0; j < 8; j++) cf[f][j] = make_float4(0.f, 0.f, 0.f, 0.f);

    int lrow = tid >> 3;          // 0..31
    int lcol = (tid & 7) << 2;    // 0,4,...,28

    for (int k0 = 0; k0 < DMODEL; k0 += 32) {
        float4 a[8];
#pragma unroll
        for (int i = 0; i < 8; i++)
            a[i] = *(const float4*)(A + (size_t)(m0 + 32 * i + lrow) * DMODEL + k0 + lcol);
        float4 w0 = *(const float4*)(W + (size_t)(n0 + lrow) * DMODEL + k0 + lcol);
        float4 w1 = *(const float4*)(W + (size_t)(n0 + 32 + lrow) * DMODEL + k0 + lcol);
        __syncthreads();
#pragma unroll
        for (int i = 0; i < 8; i++)
            *(uint4*)&As[(32 * i + lrow) * 36 + lcol] = cvt4(a[i]);
        *(uint4*)&Ws[lrow * 36 + lcol] = cvt4(w0);
        *(uint4*)&Ws[(32 + lrow) * 36 + lcol] = cvt4(w1);
        __syncthreads();

#pragma unroll
        for (int ks = 0; ks < 4; ks++) {
            unsigned aa[8];
            int rbase = (32 * w + g) * 36 + 8 * ks + t;
            aa[0] = As[rbase];
            aa[1] = As[rbase + 8 * 36];
            aa[2] = As[rbase + 4];
            aa[3] = As[rbase + 8 * 36 + 4];
            aa[4] = As[rbase + 16 * 36];
            aa[5] = As[rbase + 24 * 36];
            aa[6] = As[rbase + 16 * 36 + 4];
            aa[7] = As[rbase + 24 * 36 + 4];
#pragma unroll
            for (int j = 0; j < 8; j++) {
                unsigned b0 = Ws[(8 * j + g) * 36 + 8 * ks + t];
                unsigned b1 = Ws[(8 * j + g) * 36 + 8 * ks + t + 4];
                mma8(cf[0][j], aa, b0, b1);
                mma8(cf[1][j], aa + 4, b0, b1);
            }
        }
    }
}

// Fused Q/K/V projection: blockIdx.z selects which weight/bias/destination.
__global__ __launch_bounds__(256) void proj_qkv_kernel(
    const float* __restrict__ A,
    const float* __restrict__ Wq, const float* __restrict__ bq,
    const float* __restrict__ Wk, const float* __restrict__ bk,
    const float* __restrict__ Wv, const float* __restrict__ bv)
{
    int which = blockIdx.z;
    const float* W    = (which == 0) ? Wq : (which == 1) ? Wk : Wv;
    const float* bias = (which == 0) ? bq : (which == 1) ? bk : bv;
    float* dst        = (which == 0) ? g_q : (which == 1) ? g_k : g_v;

    float4 cf[2][8];
    int m0 = blockIdx.y * 256, n0 = blockIdx.x * 64;
    gemm_mma_core(A, W, m0, n0, cf);

    int tid = threadIdx.x;
    int w = tid >> 5, lane = tid & 31;
    int g = lane >> 2, t = lane & 3;

#pragma unroll
    for (int f = 0; f < 2; f++) {
        int m_a = m0 + 32 * w + g + 16 * f;
        int m_b = m_a + 8;
#pragma unroll
        for (int j = 0; j < 8; j++) {
            int c = n0 + 8 * j + 2 * t;          // even, c&31 <= 30
            int h = c >> 5, d = c & 31;
            float b0 = __ldg(bias + c), b1 = __ldg(bias + c + 1);
            {
                int b = m_a >> 10, n = m_a & 1023;
                float* p = dst + (((size_t)(b * HEADS + h)) * NSEQ + n) * DKDIM + d;
                p[0] = cf[f][j].x + b0; p[1] = cf[f][j].y + b1;
            }
            {
                int b = m_b >> 10, n = m_b & 1023;
                float* p = dst + (((size_t)(b * HEADS + h)) * NSEQ + n) * DKDIM + d;
                p[0] = cf[f][j].z + b0; p[1] = cf[f][j].w + b1;
            }
        }
    }
}

__global__ __launch_bounds__(256) void out_proj_kernel(
    const float* __restrict__ W, const float* __restrict__ bias,
    float* __restrict__ C)
{
    float4 cf[2][8];
    int m0 = blockIdx.y * 256, n0 = blockIdx.x * 64;
    gemm_mma_core(g_o, W, m0, n0, cf);

    int tid = threadIdx.x;
    int w = tid >> 5, lane = tid & 31;
    int g = lane >> 2, t = lane & 3;
#pragma unroll
    for (int f = 0; f < 2; f++) {
        int m_a = m0 + 32 * w + g + 16 * f;
#pragma unroll
        for (int j = 0; j < 8; j++) {
            int c = n0 + 8 * j + 2 * t;
            float b0 = __ldg(bias + c), b1 = __ldg(bias + c + 1);
            *(float2*)(C + (size_t)m_a * DMODEL + c) =
                make_float2(cf[f][j].x + b0, cf[f][j].y + b1);
            *(float2*)(C + (size_t)(m_a + 8) * DMODEL + c) =
                make_float2(cf[f][j].z + b0, cf[f][j].w + b1);
        }
    }
}

// ---------------------------------------------------------------------------
// Fused flash attention, tf32 mma, arithmetic relative-position bias.
// Block: 128 threads (4 warps), 128 query rows; warp w owns q-rows
// 32w..32w+31 (two A fragments -> every K/V/P B-fragment feeds 2 MMAs).
// Key tiles of 64. Q fragments persist in registers.
// K/V staging coalesced (4 lines per LDG.128). Bias index math hoisted:
// idx(q,k) = rc(q) - (kb>>5)*63 - cc0(k-kb); adjacent column = idx-1.
// SMEM strides: Ks 36 (bank 4g+t), Vs 40 (8t+g), Ps 68 (4g+t).
// ---------------------------------------------------------------------------
#define ATTN_SMEM_WORDS (64 * 36 + 64 * 40 + 128 * 68)

__global__ __launch_bounds__(128) void attn_kernel(
    const float* __restrict__ bias_table)
{
    extern __shared__ unsigned sm_u[];
    unsigned* Ks = sm_u;                       // 64*36
    unsigned* Vs = sm_u + 64 * 36;             // 64*40
    unsigned* Ps = sm_u + 64 * 36 + 64 * 40;   // 128*68

    const float SCALE = 0.17677669529663687f;  // 1/sqrt(32)

    int bh = blockIdx.y;                 // 0..127
    int h = bh & (HEADS - 1);
    int b = bh >> 3;
    int qbase = blockIdx.x * 128;
    int tid = threadIdx.x;
    int w = tid >> 5, lane = tid & 31;
    int g = lane >> 2, t = lane & 3;

    const float* qptr = g_q + (size_t)bh * NSEQ * DKDIM;
    const float* kptr = g_k + (size_t)bh * NSEQ * DKDIM;
    const float* vptr = g_v + (size_t)bh * NSEQ * DKDIM;
    const float* brow = bias_table + h * NUMREL;

    int r0 = qbase + 32 * w + g;   // warp's first fragment row

    // --- Q fragments (persist): frag f covers rows r0+16f, r0+16f+8 ---
    unsigned qa[4][8];
#pragma unroll
    for (int f = 0; f < 2; f++) {
        const float* qA = qptr + (size_t)(r0 + 16 * f) * DKDIM;
        const float* qB = qA + 8 * DKDIM;
#pragma unroll
        for (int ks = 0; ks < 4; ks++) {
            qa[ks][4 * f + 0] = f2tf(__ldg(qA + 8 * ks + t));
            qa[ks][4 * f + 1] = f2tf(__ldg(qB + 8 * ks + t));
            qa[ks][4 * f + 2] = f2tf(__ldg(qA + 8 * ks + t + 4));
            qa[ks][4 * f + 3] = f2tf(__ldg(qB + 8 * ks + t + 4));
        }
    }

    // rowcodes for arithmetic rel-index (rows r0, r0+8, r0+16, r0+24)
    int rc[4];
#pragma unroll
    for (int i = 0; i < 4; i++) {
        int qr = r0 + 8 * i;
        rc[i] = (qr >> 5) * 63 + (qr & 31) + 1984;
    }
    // per-thread column codes for k-offset x = 8j + 2t (invariant over kb)
    int cc0[8];
#pragma unroll
    for (int j = 0; j < 8; j++) {
        int x = 8 * j + 2 * t;
        cc0[j] = (x >> 5) * 63 + (x & 31);
    }

    float m[4], l[4];
    float4 of[2][4];
#pragma unroll
    for (int i = 0; i < 4; i++) { m[i] = -1e30f; l[i] = 0.f; }
#pragma unroll
    for (int f = 0; f < 2; f++)
#pragma unroll
        for (int jj = 0; jj < 4; jj++) of[f][jj] = make_float4(0.f, 0.f, 0.f, 0.f);

    int lrow = tid >> 3;          // 0..15
    int lcol = (tid & 7) << 2;    // 0,4,...,28

    for (int kb = 0; kb < NSEQ; kb += 64) {
        // ---- stage K,V coalesced (4 lines per LDG.128), cvt to tf32 ----
        float4 kr[4], vr[4];
#pragma unroll
        for (int i = 0; i < 4; i++) {
            kr[i] = *(const float4*)(kptr + (size_t)(kb + 16 * i + lrow) * DKDIM + lcol);
            vr[i] = *(const float4*)(vptr + (size_t)(kb + 16 * i + lrow) * DKDIM + lcol);
        }
        __syncthreads();   // prior tile's mma reads of Ks/Vs complete
#pragma unroll
        for (int i = 0; i < 4; i++) {
            *(uint4*)&Ks[(16 * i + lrow) * 36 + lcol] = cvt4(kr[i]);
            *(uint4*)&Vs[(16 * i + lrow) * 40 + lcol] = cvt4(vr[i]);
        }
        __syncthreads();

        // ---- S = Q K^T : 8 n-tiles x 4 k-steps, 2 M-frags per B load ----
        float4 sf[2][8];
#pragma unroll
        for (int f = 0; f < 2; f++)
#pragma unroll
            for (int j = 0; j < 8; j++) sf[f][j] = make_float4(0.f, 0.f, 0.f, 0.f);
#pragma unroll
        for (int ks = 0; ks < 4; ks++) {
#pragma unroll
            for (int j = 0; j < 8; j++) {
                unsigned b0 = Ks[(8 * j + g) * 36 + 8 * ks + t];
                unsigned b1 = Ks[(8 * j + g) * 36 + 8 * ks + t + 4];
                mma8(sf[0][j], &qa[ks][0], b0, b1);
                mma8(sf[1][j], &qa[ks][4], b0, b1);
            }
        }

        // ---- bias + online softmax on fragments ----
        int koff = (kb >> 5) * 63;
        int base0 = rc[0] - koff, base1 = rc[1] - koff;
        int base2 = rc[2] - koff, base3 = rc[3] - koff;

        float mx[4] = {-1e30f, -1e30f, -1e30f, -1e30f};
#pragma unroll
        for (int j = 0; j < 8; j++) {
            int iA0 = base0 - cc0[j];
            int iA1 = base1 - cc0[j];
            int iA2 = base2 - cc0[j];
            int iA3 = base3 - cc0[j];
            sf[0][j].x = fmaf(sf[0][j].x, SCALE, __ldg(brow + iA0));
            sf[0][j].y = fmaf(sf[0][j].y, SCALE, __ldg(brow + iA0 - 1));
            sf[0][j].z = fmaf(sf[0][j].z, SCALE, __ldg(brow + iA1));
            sf[0][j].w = fmaf(sf[0][j].w, SCALE, __ldg(brow + iA1 - 1));
            sf[1][j].x = fmaf(sf[1][j].x, SCALE, __ldg(brow + iA2));
            sf[1][j].y = fmaf(sf[1][j].y, SCALE, __ldg(brow + iA2 - 1));
            sf[1][j].z = fmaf(sf[1][j].z, SCALE, __ldg(brow + iA3));
            sf[1][j].w = fmaf(sf[1][j].w, SCALE, __ldg(brow + iA3 - 1));
            mx[0] = fmaxf(mx[0], fmaxf(sf[0][j].x, sf[0][j].y));
            mx[1] = fmaxf(mx[1], fmaxf(sf[0][j].z, sf[0][j].w));
            mx[2] = fmaxf(mx[2], fmaxf(sf[1][j].x, sf[1][j].y));
            mx[3] = fmaxf(mx[3], fmaxf(sf[1][j].z, sf[1][j].w));
        }
        float fac[4], s[4];
#pragma unroll
        for (int i = 0; i < 4; i++) {
            mx[i] = fmaxf(mx[i], __shfl_xor_sync(0xffffffffu, mx[i], 1));
            mx[i] = fmaxf(mx[i], __shfl_xor_sync(0xffffffffu, mx[i], 2));
            float nm = fmaxf(m[i], mx[i]);
            fac[i] = __expf(m[i] - nm);
            m[i] = nm;
            s[i] = 0.f;
        }
#pragma unroll
        for (int f = 0; f < 2; f++) {
#pragma unroll
            for (int j = 0; j < 8; j++) {
                sf[f][j].x = __expf(sf[f][j].x - m[2 * f]);
                sf[f][j].y = __expf(sf[f][j].y - m[2 * f]);
                sf[f][j].z = __expf(sf[f][j].z - m[2 * f + 1]);
                sf[f][j].w = __expf(sf[f][j].w - m[2 * f + 1]);
                s[2 * f]     += sf[f][j].x + sf[f][j].y;
                s[2 * f + 1] += sf[f][j].z + sf[f][j].w;
                uint2 p0; p0.x = f2tf(sf[f][j].x); p0.y = f2tf(sf[f][j].y);
                uint2 p1; p1.x = f2tf(sf[f][j].z); p1.y = f2tf(sf[f][j].w);
                *(uint2*)&Ps[(32 * w + g + 16 * f) * 68 + 8 * j + 2 * t] = p0;
                *(uint2*)&Ps[(32 * w + g + 16 * f + 8) * 68 + 8 * j + 2 * t] = p1;
            }
        }
#pragma unroll
        for (int i = 0; i < 4; i++) {
            s[i] += __shfl_xor_sync(0xffffffffu, s[i], 1);
            s[i] += __shfl_xor_sync(0xffffffffu, s[i], 2);
            l[i] = l[i] * fac[i] + s[i];
        }
#pragma unroll
        for (int f = 0; f < 2; f++)
#pragma unroll
            for (int jj = 0; jj < 4; jj++) {
                of[f][jj].x *= fac[2 * f];     of[f][jj].y *= fac[2 * f];
                of[f][jj].z *= fac[2 * f + 1]; of[f][jj].w *= fac[2 * f + 1];
            }
        __syncwarp();   // warp's own P rows visible

        // ---- O += P @ V : 4 n-tiles x 8 k-steps, 2 M-frags per B load ----
#pragma unroll
        for (int ks = 0; ks < 8; ks++) {
            unsigned pa[8];
            int pbase = (32 * w + g) * 68 + 8 * ks + t;
            pa[0] = Ps[pbase];
            pa[1] = Ps[pbase + 8 * 68];
            pa[2] = Ps[pbase + 4];
            pa[3] = Ps[pbase + 8 * 68 + 4];
            pa[4] = Ps[pbase + 16 * 68];
            pa[5] = Ps[pbase + 24 * 68];
            pa[6] = Ps[pbase + 16 * 68 + 4];
            pa[7] = Ps[pbase + 24 * 68 + 4];
#pragma unroll
            for (int jj = 0; jj < 4; jj++) {
                unsigned b0 = Vs[(8 * ks + t) * 40 + 8 * jj + g];
                unsigned b1 = Vs[(8 * ks + t + 4) * 40 + 8 * jj + g];
                mma8(of[0][jj], pa, b0, b1);
                mma8(of[1][jj], pa + 4, b0, b1);
            }
        }
    }

    // ---- normalize + write O in [B, N, H*dk] layout ----
#pragma unroll
    for (int f = 0; f < 2; f++) {
        float inv0 = 1.0f / l[2 * f], inv1 = 1.0f / l[2 * f + 1];
        int qrA = r0 + 16 * f, qrB = qrA + 8;
#pragma unroll
        for (int jj = 0; jj < 4; jj++) {
            int col = h * DKDIM + 8 * jj + 2 * t;
            *(float2*)(g_o + ((size_t)b * NSEQ + qrA) * DMODEL + col) =
                make_float2(of[f][jj].x * inv0, of[f][jj].y * inv0);
            *(float2*)(g_o + ((size_t)b * NSEQ + qrB) * DMODEL + col) =
                make_float2(of[f][jj].z * inv1, of[f][jj].w * inv1);
        }
    }
}

// ---------------------------------------------------------------------------
extern "C" void kernel_launch(void* const* d_in, const int* in_sizes, int n_in,
                              void* d_out, int out_size)
{
    const float* x          = (const float*)d_in[0];
    const float* Wq         = (const float*)d_in[1];
    const float* bq         = (const float*)d_in[2];
    const float* Wk         = (const float*)d_in[3];
    const float* bk         = (const float*)d_in[4];
    const float* Wv         = (const float*)d_in[5];
    const float* bv         = (const float*)d_in[6];
    const float* Wo         = (const float*)d_in[7];
    const float* bo         = (const float*)d_in[8];
    const float* bias_table = (const float*)d_in[9];
    float* out = (float*)d_out;

    cudaFuncSetAttribute(attn_kernel,
                         cudaFuncAttributeMaxDynamicSharedMemorySize,
                         ATTN_SMEM_WORDS * 4);

    dim3 pgrid(DMODEL / 64, (BATCH * NSEQ) / 256, 3);   // (4, 64, 3)
    proj_qkv_kernel<<<pgrid, 256>>>(x, Wq, bq, Wk, bk, Wv, bv);

    attn_kernel<<<dim3(NSEQ / 128, BATCH * HEADS), 128,
                  ATTN_SMEM_WORDS * 4>>>(bias_table);

    dim3 ogrid(DMODEL / 64, (BATCH * NSEQ) / 256);      // (4, 64)
    out_proj_kernel<<<ogrid, 256>>>(Wo, bo, out);
}

// round 7
// speedup vs baseline: 4.0224x; 1.0001x over previous
#include <cuda_runtime.h>
#include <math.h>

#define BATCH  16
#define NSEQ   1024
#define DMODEL 256
#define HEADS  8
#define DKDIM  32
#define NUMREL 3969

#define LOG2E   1.4426950408889634f
#define QSL2E   0.2550697345602283f   /* (1/sqrt(32)) * log2(e) */

// Scratch (allocation-free rule: __device__ globals). tf32 bit patterns.
__device__ unsigned g_q[BATCH * HEADS * NSEQ * DKDIM];
__device__ unsigned g_k[BATCH * HEADS * NSEQ * DKDIM];
__device__ unsigned g_v[BATCH * HEADS * NSEQ * DKDIM];
__device__ unsigned g_o[BATCH * NSEQ * DMODEL];
__device__ unsigned g_xt[BATCH * NSEQ * DMODEL];     // x as tf32
__device__ unsigned g_wt[4 * DMODEL * DMODEL];       // Wq,Wk,Wv,Wo as tf32

// ----------------------- helpers ------------------------------------------
__device__ __forceinline__ unsigned f2tf(float f) {
    unsigned u;
    asm("cvt.rna.tf32.f32 %0, %1;" : "=r"(u) : "f"(f));
    return u;
}
__device__ __forceinline__ uint4 cvt4(float4 a) {
    uint4 u;
    u.x = f2tf(a.x); u.y = f2tf(a.y); u.z = f2tf(a.z); u.w = f2tf(a.w);
    return u;
}
__device__ __forceinline__ float ex2(float x) {
    float r;
    asm("ex2.approx.f32 %0, %1;" : "=f"(r) : "f"(x));
    return r;
}
__device__ __forceinline__ void cp16(unsigned dst, const void* src) {
    asm volatile("cp.async.cg.shared.global [%0], [%1], 16;"
                 :: "r"(dst), "l"(src) : "memory");
}
__device__ __forceinline__ void cp_commit() {
    asm volatile("cp.async.commit_group;" ::: "memory");
}
__device__ __forceinline__ void cp_wait0() {
    asm volatile("cp.async.wait_group 0;" ::: "memory");
}

// D(16x8,f32) += A(16x8,tf32) * B(8x8,tf32)
__device__ __forceinline__ void mma8(float4& d, const unsigned* a,
                                     unsigned b0, unsigned b1) {
    asm volatile(
        "mma.sync.aligned.m16n8k8.row.col.f32.tf32.tf32.f32 "
        "{%0,%1,%2,%3},{%4,%5,%6,%7},{%8,%9},{%0,%1,%2,%3};"
        : "+f"(d.x), "+f"(d.y), "+f"(d.z), "+f"(d.w)
        : "r"(a[0]), "r"(a[1]), "r"(a[2]), "r"(a[3]), "r"(b0), "r"(b1));
}

// ---------------------------------------------------------------------------
// Prep: convert x and the 4 weight matrices to tf32 bits (once).
// ---------------------------------------------------------------------------
__global__ void prep_kernel(const float* __restrict__ x,
                            const float* __restrict__ wq,
                            const float* __restrict__ wk,
                            const float* __restrict__ wv,
                            const float* __restrict__ wo)
{
    int idx = blockIdx.x * blockDim.x + threadIdx.x;
    int stride = gridDim.x * blockDim.x;
    const int NX = BATCH * NSEQ * DMODEL / 4;
    for (int i = idx; i < NX; i += stride)
        ((uint4*)g_xt)[i] = cvt4(((const float4*)x)[i]);
    const int NW = DMODEL * DMODEL / 4;
    for (int i = idx; i < NW; i += stride) {
        ((uint4*)(g_wt            ))[i] = cvt4(((const float4*)wq)[i]);
        ((uint4*)(g_wt +     65536))[i] = cvt4(((const float4*)wk)[i]);
        ((uint4*)(g_wt + 2 * 65536))[i] = cvt4(((const float4*)wv)[i]);
        ((uint4*)(g_wt + 3 * 65536))[i] = cvt4(((const float4*)wo)[i]);
    }
}

// ---------------------------------------------------------------------------
// GEMM core: C = A @ W^T. Out tile 256(M) x 64(N), 256 thr, 8 warps;
// warp w owns rows 32w..32w+31. BK=32. All operands pre-converted tf32.
// cp.async double-buffered staging, one barrier per K-step.
// SMEM layout (words): A0 A1 W0 W1.
// ---------------------------------------------------------------------------
#define GS_AW (256 * 36)
#define GS_WW (64 * 36)
#define GEMM_SMEM_WORDS (2 * GS_AW + 2 * GS_WW)   // 23040 words = 92160 B

__device__ __forceinline__ void gemm_mma_core(
    const unsigned* __restrict__ A, const unsigned* __restrict__ W,
    int m0, int n0, float4 cf[2][8])
{
    extern __shared__ unsigned sm[];
    unsigned sb = (unsigned)__cvta_generic_to_shared(sm);

    int tid = threadIdx.x;
    int w = tid >> 5, lane = tid & 31;
    int g = lane >> 2, t = lane & 3;
    int rr = tid >> 3;            // 0..31
    int cc = (tid & 7) << 2;      // 0,4,...,28 (words)

#pragma unroll
    for (int f = 0; f < 2; f++)
#pragma unroll
        for (int j = 0; j < 8; j++) cf[f][j] = make_float4(0.f, 0.f, 0.f, 0.f);

    auto copy_stage = [&](int k0, int buf) {
        unsigned ab = sb + buf * (GS_AW * 4);
        unsigned wb = sb + (2 * GS_AW + buf * GS_WW) * 4;
#pragma unroll
        for (int i = 0; i < 8; i++) {
            int row = 32 * i + rr;
            cp16(ab + (row * 36 + cc) * 4,
                 A + (size_t)(m0 + row) * DMODEL + k0 + cc);
        }
#pragma unroll
        for (int i = 0; i < 2; i++) {
            int row = 32 * i + rr;
            cp16(wb + (row * 36 + cc) * 4,
                 W + (size_t)(n0 + row) * DMODEL + k0 + cc);
        }
        cp_commit();
    };

    copy_stage(0, 0);

    for (int s = 0; s < 8; s++) {
        cp_wait0();
        __syncthreads();
        if (s < 7) copy_stage(32 * (s + 1), (s + 1) & 1);

        const unsigned* Ab = sm + (s & 1) * GS_AW;
        const unsigned* Wb = sm + 2 * GS_AW + (s & 1) * GS_WW;

#pragma unroll
        for (int ks = 0; ks < 4; ks++) {
            unsigned aa[8];
            int rbase = (32 * w + g) * 36 + 8 * ks + t;
            aa[0] = Ab[rbase];
            aa[1] = Ab[rbase + 8 * 36];
            aa[2] = Ab[rbase + 4];
            aa[3] = Ab[rbase + 8 * 36 + 4];
            aa[4] = Ab[rbase + 16 * 36];
            aa[5] = Ab[rbase + 24 * 36];
            aa[6] = Ab[rbase + 16 * 36 + 4];
            aa[7] = Ab[rbase + 24 * 36 + 4];
#pragma unroll
            for (int j = 0; j < 8; j++) {
                unsigned b0 = Wb[(8 * j + g) * 36 + 8 * ks + t];
                unsigned b1 = Wb[(8 * j + g) * 36 + 8 * ks + t + 4];
                mma8(cf[0][j], aa, b0, b1);
                mma8(cf[1][j], aa + 4, b0, b1);
            }
        }
    }
}

// Fused Q/K/V projection: blockIdx.z selects weight/bias/destination.
// Epilogue: +bias in f32, Q additionally scaled by (1/sqrt(dk))*log2e,
// store tf32 bits in [b,h,n,d] scratch.
__global__ __launch_bounds__(256) void proj_qkv_kernel(
    const float* __restrict__ bq, const float* __restrict__ bk,
    const float* __restrict__ bv)
{
    int which = blockIdx.z;
    const unsigned* W  = g_wt + which * 65536;
    const float* bias  = (which == 0) ? bq : (which == 1) ? bk : bv;
    unsigned* dst      = (which == 0) ? g_q : (which == 1) ? g_k : g_v;
    float sc           = (which == 0) ? QSL2E : 1.0f;

    float4 cf[2][8];
    int m0 = blockIdx.y * 256, n0 = blockIdx.x * 64;
    gemm_mma_core(g_xt, W, m0, n0, cf);

    int tid = threadIdx.x;
    int w = tid >> 5, lane = tid & 31;
    int g = lane >> 2, t = lane & 3;

#pragma unroll
    for (int f = 0; f < 2; f++) {
        int m_a = m0 + 32 * w + g + 16 * f;
        int m_b = m_a + 8;
#pragma unroll
        for (int j = 0; j < 8; j++) {
            int c = n0 + 8 * j + 2 * t;          // even, c&31 <= 30
            int h = c >> 5, d = c & 31;
            float b0 = __ldg(bias + c), b1 = __ldg(bias + c + 1);
            {
                int b = m_a >> 10, n = m_a & 1023;
                unsigned* p = dst + (((size_t)(b * HEADS + h)) * NSEQ + n) * DKDIM + d;
                p[0] = f2tf((cf[f][j].x + b0) * sc);
                p[1] = f2tf((cf[f][j].y + b1) * sc);
            }
            {
                int b = m_b >> 10, n = m_b & 1023;
                unsigned* p = dst + (((size_t)(b * HEADS + h)) * NSEQ + n) * DKDIM + d;
                p[0] = f2tf((cf[f][j].z + b0) * sc);
                p[1] = f2tf((cf[f][j].w + b1) * sc);
            }
        }
    }
}

__global__ __launch_bounds__(256) void out_proj_kernel(
    const float* __restrict__ bias, float* __restrict__ C)
{
    float4 cf[2][8];
    int m0 = blockIdx.y * 256, n0 = blockIdx.x * 64;
    gemm_mma_core(g_o, g_wt + 3 * 65536, m0, n0, cf);

    int tid = threadIdx.x;
    int w = tid >> 5, lane = tid & 31;
    int g = lane >> 2, t = lane & 3;
#pragma unroll
    for (int f = 0; f < 2; f++) {
        int m_a = m0 + 32 * w + g + 16 * f;
#pragma unroll
        for (int j = 0; j < 8; j++) {
            int c = n0 + 8 * j + 2 * t;
            float b0 = __ldg(bias + c), b1 = __ldg(bias + c + 1);
            *(float2*)(C + (size_t)m_a * DMODEL + c) =
                make_float2(cf[f][j].x + b0, cf[f][j].y + b1);
            *(float2*)(C + (size_t)(m_a + 8) * DMODEL + c) =
                make_float2(cf[f][j].z + b0, cf[f][j].w + b1);
        }
    }
}

// ---------------------------------------------------------------------------
// Fused flash attention (log2-domain softmax), tf32 mma, arithmetic rel bias.
// Block: 128 threads (4 warps), 128 query rows; warp w owns rows 32w..32w+31.
// Q pre-scaled by (1/sqrt(dk))*log2e at projection. All operands tf32 bits.
// K/V staged via cp.async double buffer; one barrier per 64-key tile.
// 16 key tiles (NSEQ/64).   <-- round-6 bug was s<8 here.
// SMEM (words): K0 K1 V0 V1 Ps. Strides: K 36, V 40, P 68 (bank-audited).
// ---------------------------------------------------------------------------
#define AT_KW (64 * 36)
#define AT_VW (64 * 40)
#define AT_PS (128 * 68)
#define ATTN_SMEM_WORDS (2 * AT_KW + 2 * AT_VW + AT_PS)   // 18432 w = 73728 B

__global__ __launch_bounds__(128) void attn_kernel(
    const float* __restrict__ bias_table)
{
    extern __shared__ unsigned sm[];
    unsigned sb = (unsigned)__cvta_generic_to_shared(sm);
    unsigned* Ps = sm + 2 * AT_KW + 2 * AT_VW;

    int bh = blockIdx.y;                 // 0..127
    int h = bh & (HEADS - 1);
    int b = bh >> 3;
    int qbase = blockIdx.x * 128;
    int tid = threadIdx.x;
    int w = tid >> 5, lane = tid & 31;
    int g = lane >> 2, t = lane & 3;

    const unsigned* qptr = g_q + (size_t)bh * NSEQ * DKDIM;
    const unsigned* kptr = g_k + (size_t)bh * NSEQ * DKDIM;
    const unsigned* vptr = g_v + (size_t)bh * NSEQ * DKDIM;
    const float* brow = bias_table + h * NUMREL;

    int r0 = qbase + 32 * w + g;   // warp's first fragment row
    int rr = tid >> 3;             // 0..15
    int cc = (tid & 7) << 2;       // 0,4,...,28

    auto copy_kv = [&](int kb, int buf) {
        unsigned ksm = sb + buf * (AT_KW * 4);
        unsigned vsm = sb + (2 * AT_KW + buf * AT_VW) * 4;
#pragma unroll
        for (int i = 0; i < 4; i++) {
            int row = 16 * i + rr;
            cp16(ksm + (row * 36 + cc) * 4,
                 kptr + (size_t)(kb + row) * DKDIM + cc);
            cp16(vsm + (row * 40 + cc) * 4,
                 vptr + (size_t)(kb + row) * DKDIM + cc);
        }
        cp_commit();
    };

    // --- Q fragments (persist): frag f covers rows r0+16f, r0+16f+8 ---
    unsigned qa[4][8];
#pragma unroll
    for (int f = 0; f < 2; f++) {
        const unsigned* qA = qptr + (size_t)(r0 + 16 * f) * DKDIM;
        const unsigned* qB = qA + 8 * DKDIM;
#pragma unroll
        for (int ks = 0; ks < 4; ks++) {
            qa[ks][4 * f + 0] = __ldg(qA + 8 * ks + t);
            qa[ks][4 * f + 1] = __ldg(qB + 8 * ks + t);
            qa[ks][4 * f + 2] = __ldg(qA + 8 * ks + t + 4);
            qa[ks][4 * f + 3] = __ldg(qB + 8 * ks + t + 4);
        }
    }

    // rowcodes for arithmetic rel-index (rows r0, r0+8, r0+16, r0+24)
    int rc[4];
#pragma unroll
    for (int i = 0; i < 4; i++) {
        int qr = r0 + 8 * i;
        rc[i] = (qr >> 5) * 63 + (qr & 31) + 1984;
    }
    int cc0[8];
#pragma unroll
    for (int j = 0; j < 8; j++) {
        int x = 8 * j + 2 * t;
        cc0[j] = (x >> 5) * 63 + (x & 31);
    }

    float m[4], l[4];
    float4 of[2][4];
#pragma unroll
    for (int i = 0; i < 4; i++) { m[i] = -1e30f; l[i] = 0.f; }
#pragma unroll
    for (int f = 0; f < 2; f++)
#pragma unroll
        for (int jj = 0; jj < 4; jj++) of[f][jj] = make_float4(0.f, 0.f, 0.f, 0.f);

    copy_kv(0, 0);

    for (int s = 0; s < 16; s++) {        // 16 key tiles = NSEQ/64
        int kb = 64 * s;
        cp_wait0();
        __syncthreads();
        if (s < 15) copy_kv(kb + 64, (s + 1) & 1);

        const unsigned* Kb = sm + (s & 1) * AT_KW;
        const unsigned* Vb = sm + 2 * AT_KW + (s & 1) * AT_VW;

        // ---- S = Q K^T : 8 n-tiles x 4 k-steps, 2 M-frags per B load ----
        float4 sf[2][8];
#pragma unroll
        for (int f = 0; f < 2; f++)
#pragma unroll
            for (int j = 0; j < 8; j++) sf[f][j] = make_float4(0.f, 0.f, 0.f, 0.f);
#pragma unroll
        for (int ks = 0; ks < 4; ks++) {
#pragma unroll
            for (int j = 0; j < 8; j++) {
                unsigned b0 = Kb[(8 * j + g) * 36 + 8 * ks + t];
                unsigned b1 = Kb[(8 * j + g) * 36 + 8 * ks + t + 4];
                mma8(sf[0][j], &qa[ks][0], b0, b1);
                mma8(sf[1][j], &qa[ks][4], b0, b1);
            }
        }

        // ---- bias + online softmax (log2 domain) ----
        int koff = (kb >> 5) * 63;
        int base0 = rc[0] - koff, base1 = rc[1] - koff;
        int base2 = rc[2] - koff, base3 = rc[3] - koff;

        float mx[4] = {-1e30f, -1e30f, -1e30f, -1e30f};
#pragma unroll
        for (int j = 0; j < 8; j++) {
            int iA0 = base0 - cc0[j];
            int iA1 = base1 - cc0[j];
            int iA2 = base2 - cc0[j];
            int iA3 = base3 - cc0[j];
            sf[0][j].x = fmaf(__ldg(brow + iA0),     LOG2E, sf[0][j].x);
            sf[0][j].y = fmaf(__ldg(brow + iA0 - 1), LOG2E, sf[0][j].y);
            sf[0][j].z = fmaf(__ldg(brow + iA1),     LOG2E, sf[0][j].z);
            sf[0][j].w = fmaf(__ldg(brow + iA1 - 1), LOG2E, sf[0][j].w);
            sf[1][j].x = fmaf(__ldg(brow + iA2),     LOG2E, sf[1][j].x);
            sf[1][j].y = fmaf(__ldg(brow + iA2 - 1), LOG2E, sf[1][j].y);
            sf[1][j].z = fmaf(__ldg(brow + iA3),     LOG2E, sf[1][j].z);
            sf[1][j].w = fmaf(__ldg(brow + iA3 - 1), LOG2E, sf[1][j].w);
            mx[0] = fmaxf(mx[0], fmaxf(sf[0][j].x, sf[0][j].y));
            mx[1] = fmaxf(mx[1], fmaxf(sf[0][j].z, sf[0][j].w));
            mx[2] = fmaxf(mx[2], fmaxf(sf[1][j].x, sf[1][j].y));
            mx[3] = fmaxf(mx[3], fmaxf(sf[1][j].z, sf[1][j].w));
        }
        float fac[4], s4[4];
#pragma unroll
        for (int i = 0; i < 4; i++) {
            mx[i] = fmaxf(mx[i], __shfl_xor_sync(0xffffffffu, mx[i], 1));
            mx[i] = fmaxf(mx[i], __shfl_xor_sync(0xffffffffu, mx[i], 2));
            float nm = fmaxf(m[i], mx[i]);
            fac[i] = ex2(m[i] - nm);
            m[i] = nm;
            s4[i] = 0.f;
        }
#pragma unroll
        for (int f = 0; f < 2; f++) {
#pragma unroll
            for (int j = 0; j < 8; j++) {
                sf[f][j].x = ex2(sf[f][j].x - m[2 * f]);
                sf[f][j].y = ex2(sf[f][j].y - m[2 * f]);
                sf[f][j].z = ex2(sf[f][j].z - m[2 * f + 1]);
                sf[f][j].w = ex2(sf[f][j].w - m[2 * f + 1]);
                s4[2 * f]     += sf[f][j].x + sf[f][j].y;
                s4[2 * f + 1] += sf[f][j].z + sf[f][j].w;
                uint2 p0; p0.x = f2tf(sf[f][j].x); p0.y = f2tf(sf[f][j].y);
                uint2 p1; p1.x = f2tf(sf[f][j].z); p1.y = f2tf(sf[f][j].w);
                *(uint2*)&Ps[(32 * w + g + 16 * f) * 68 + 8 * j + 2 * t] = p0;
                *(uint2*)&Ps[(32 * w + g + 16 * f + 8) * 68 + 8 * j + 2 * t] = p1;
            }
        }
#pragma unroll
        for (int i = 0; i < 4; i++) {
            s4[i] += __shfl_xor_sync(0xffffffffu, s4[i], 1);
            s4[i] += __shfl_xor_sync(0xffffffffu, s4[i], 2);
            l[i] = l[i] * fac[i] + s4[i];
        }
#pragma unroll
        for (int f = 0; f < 2; f++)
#pragma unroll
            for (int jj = 0; jj < 4; jj++) {
                of[f][jj].x *= fac[2 * f];     of[f][jj].y *= fac[2 * f];
                of[f][jj].z *= fac[2 * f + 1]; of[f][jj].w *= fac[2 * f + 1];
            }
        __syncwarp();   // warp's own P rows visible

        // ---- O += P @ V : 4 n-tiles x 8 k-steps, 2 M-frags per B load ----
#pragma unroll
        for (int ks = 0; ks < 8; ks++) {
            unsigned pa[8];
            int pbase = (32 * w + g) * 68 + 8 * ks + t;
            pa[0] = Ps[pbase];
            pa[1] = Ps[pbase + 8 * 68];
            pa[2] = Ps[pbase + 4];
            pa[3] = Ps[pbase + 8 * 68 + 4];
            pa[4] = Ps[pbase + 16 * 68];
            pa[5] = Ps[pbase + 24 * 68];
            pa[6] = Ps[pbase + 16 * 68 + 4];
            pa[7] = Ps[pbase + 24 * 68 + 4];
#pragma unroll
            for (int jj = 0; jj < 4; jj++) {
                unsigned b0 = Vb[(8 * ks + t) * 40 + 8 * jj + g];
                unsigned b1 = Vb[(8 * ks + t + 4) * 40 + 8 * jj + g];
                mma8(of[0][jj], pa, b0, b1);
                mma8(of[1][jj], pa + 4, b0, b1);
            }
        }
    }

    // ---- normalize + write O as tf32 bits in [B, N, H*dk] layout ----
#pragma unroll
    for (int f = 0; f < 2; f++) {
        float inv0 = 1.0f / l[2 * f], inv1 = 1.0f / l[2 * f + 1];
        int qrA = r0 + 16 * f, qrB = qrA + 8;
#pragma unroll
        for (int jj = 0; jj < 4; jj++) {
            int col = h * DKDIM + 8 * jj + 2 * t;
            uint2 u0, u1;
            u0.x = f2tf(of[f][jj].x * inv0); u0.y = f2tf(of[f][jj].y * inv0);
            u1.x = f2tf(of[f][jj].z * inv1); u1.y = f2tf(of[f][jj].w * inv1);
            *(uint2*)(g_o + ((size_t)b * NSEQ + qrA) * DMODEL + col) = u0;
            *(uint2*)(g_o + ((size_t)b * NSEQ + qrB) * DMODEL + col) = u1;
        }
    }
}

// ---------------------------------------------------------------------------
extern "C" void kernel_launch(void* const* d_in, const int* in_sizes, int n_in,
                              void* d_out, int out_size)
{
    const float* x          = (const float*)d_in[0];
    const float* Wq         = (const float*)d_in[1];
    const float* bq         = (const float*)d_in[2];
    const float* Wk         = (const float*)d_in[3];
    const float* bk         = (const float*)d_in[4];
    const float* Wv         = (const float*)d_in[5];
    const float* bv         = (const float*)d_in[6];
    const float* Wo         = (const float*)d_in[7];
    const float* bo         = (const float*)d_in[8];
    const float* bias_table = (const float*)d_in[9];
    float* out = (float*)d_out;

    cudaFuncSetAttribute(attn_kernel,
                         cudaFuncAttributeMaxDynamicSharedMemorySize,
                         ATTN_SMEM_WORDS * 4);
    cudaFuncSetAttribute(proj_qkv_kernel,
                         cudaFuncAttributeMaxDynamicSharedMemorySize,
                         GEMM_SMEM_WORDS * 4);
    cudaFuncSetAttribute(out_proj_kernel,
                         cudaFuncAttributeMaxDynamicSharedMemorySize,
                         GEMM_SMEM_WORDS * 4);

    prep_kernel<<<1024, 256>>>(x, Wq, Wk, Wv, Wo);

    dim3 pgrid(DMODEL / 64, (BATCH * NSEQ) / 256, 3);   // (4, 64, 3)
    proj_qkv_kernel<<<pgrid, 256, GEMM_SMEM_WORDS * 4>>>(bq, bk, bv);

    attn_kernel<<<dim3(NSEQ / 128, BATCH * HEADS), 128,
                  ATTN_SMEM_WORDS * 4>>>(bias_table);

    dim3 ogrid(DMODEL / 64, (BATCH * NSEQ) / 256);      // (4, 64)
    out_proj_kernel<<<ogrid, 256, GEMM_SMEM_WORDS * 4>>>(bo, out);
}

// round 8
// speedup vs baseline: 4.4025x; 1.0945x over previous
#include <cuda_runtime.h>
#include <math.h>

#define BATCH  16
#define NSEQ   1024
#define DMODEL 256
#define HEADS  8
#define DKDIM  32
#define NUMREL 3969

#define LOG2E   1.4426950408889634f
#define QSL2E   0.2550697345602283f   /* (1/sqrt(32)) * log2(e) */

// Scratch (allocation-free rule: __device__ globals). tf32 bit patterns.
__device__ unsigned g_q[BATCH * HEADS * NSEQ * DKDIM];
__device__ unsigned g_k[BATCH * HEADS * NSEQ * DKDIM];
__device__ unsigned g_v[BATCH * HEADS * NSEQ * DKDIM];
__device__ unsigned g_o[BATCH * NSEQ * DMODEL];
__device__ unsigned g_xt[BATCH * NSEQ * DMODEL];     // x as tf32
__device__ unsigned g_wt[4 * DMODEL * DMODEL];       // Wq,Wk,Wv,Wo as tf32

// ----------------------- helpers ------------------------------------------
__device__ __forceinline__ unsigned f2tf(float f) {
    unsigned u;
    asm("cvt.rna.tf32.f32 %0, %1;" : "=r"(u) : "f"(f));
    return u;
}
__device__ __forceinline__ uint4 cvt4(float4 a) {
    uint4 u;
    u.x = f2tf(a.x); u.y = f2tf(a.y); u.z = f2tf(a.z); u.w = f2tf(a.w);
    return u;
}
__device__ __forceinline__ float ex2(float x) {
    float r;
    asm("ex2.approx.f32 %0, %1;" : "=f"(r) : "f"(x));
    return r;
}
__device__ __forceinline__ void cp16(unsigned dst, const void* src) {
    asm volatile("cp.async.cg.shared.global [%0], [%1], 16;"
                 :: "r"(dst), "l"(src) : "memory");
}
__device__ __forceinline__ void cp_commit() {
    asm volatile("cp.async.commit_group;" ::: "memory");
}
__device__ __forceinline__ void cp_wait0() {
    asm volatile("cp.async.wait_group 0;" ::: "memory");
}

// D(16x8,f32) += A(16x8,tf32) * B(8x8,tf32)
__device__ __forceinline__ void mma8(float4& d, const unsigned* a,
                                     unsigned b0, unsigned b1) {
    asm volatile(
        "mma.sync.aligned.m16n8k8.row.col.f32.tf32.tf32.f32 "
        "{%0,%1,%2,%3},{%4,%5,%6,%7},{%8,%9},{%0,%1,%2,%3};"
        : "+f"(d.x), "+f"(d.y), "+f"(d.z), "+f"(d.w)
        : "r"(a[0]), "r"(a[1]), "r"(a[2]), "r"(a[3]), "r"(b0), "r"(b1));
}

// ---------------------------------------------------------------------------
// Prep: convert x and the 4 weight matrices to tf32 bits (once).
// ---------------------------------------------------------------------------
__global__ void prep_kernel(const float* __restrict__ x,
                            const float* __restrict__ wq,
                            const float* __restrict__ wk,
                            const float* __restrict__ wv,
                            const float* __restrict__ wo)
{
    int idx = blockIdx.x * blockDim.x + threadIdx.x;
    int stride = gridDim.x * blockDim.x;
    const int NX = BATCH * NSEQ * DMODEL / 4;
    for (int i = idx; i < NX; i += stride)
        ((uint4*)g_xt)[i] = cvt4(((const float4*)x)[i]);
    const int NW = DMODEL * DMODEL / 4;
    for (int i = idx; i < NW; i += stride) {
        ((uint4*)(g_wt            ))[i] = cvt4(((const float4*)wq)[i]);
        ((uint4*)(g_wt +     65536))[i] = cvt4(((const float4*)wk)[i]);
        ((uint4*)(g_wt + 2 * 65536))[i] = cvt4(((const float4*)wv)[i]);
        ((uint4*)(g_wt + 3 * 65536))[i] = cvt4(((const float4*)wo)[i]);
    }
}

// ---------------------------------------------------------------------------
// GEMM core: C = A @ W^T. Out tile 128(M) x 64(N), 128 thr, 4 warps;
// warp w owns rows 32w..32w+31 (two 16-row A fragments -> each B fragment
// load feeds 2 MMAs). BK=32. All operands pre-converted tf32.
// cp.async double-buffered staging. SMEM halved vs R7 -> 4 CTAs/SM.
// ---------------------------------------------------------------------------
#define GS_AW (128 * 36)
#define GS_WW (64 * 36)
#define GEMM_SMEM_WORDS (2 * GS_AW + 2 * GS_WW)   // 13824 words = 55296 B

__device__ __forceinline__ void gemm_mma_core(
    const unsigned* __restrict__ A, const unsigned* __restrict__ W,
    int m0, int n0, float4 cf[2][8])
{
    extern __shared__ unsigned sm[];
    unsigned sb = (unsigned)__cvta_generic_to_shared(sm);

    int tid = threadIdx.x;
    int w = tid >> 5, lane = tid & 31;
    int g = lane >> 2, t = lane & 3;
    int rr = tid >> 3;            // 0..15
    int cc = (tid & 7) << 2;      // 0,4,...,28 (words)

#pragma unroll
    for (int f = 0; f < 2; f++)
#pragma unroll
        for (int j = 0; j < 8; j++) cf[f][j] = make_float4(0.f, 0.f, 0.f, 0.f);

    auto copy_stage = [&](int k0, int buf) {
        unsigned ab = sb + buf * (GS_AW * 4);
        unsigned wb = sb + (2 * GS_AW + buf * GS_WW) * 4;
#pragma unroll
        for (int i = 0; i < 8; i++) {
            int row = 16 * i + rr;
            cp16(ab + (row * 36 + cc) * 4,
                 A + (size_t)(m0 + row) * DMODEL + k0 + cc);
        }
#pragma unroll
        for (int i = 0; i < 4; i++) {
            int row = 16 * i + rr;
            cp16(wb + (row * 36 + cc) * 4,
                 W + (size_t)(n0 + row) * DMODEL + k0 + cc);
        }
        cp_commit();
    };

    copy_stage(0, 0);

    for (int s = 0; s < 8; s++) {
        cp_wait0();
        __syncthreads();
        if (s < 7) copy_stage(32 * (s + 1), (s + 1) & 1);

        const unsigned* Ab = sm + (s & 1) * GS_AW;
        const unsigned* Wb = sm + 2 * GS_AW + (s & 1) * GS_WW;

#pragma unroll
        for (int ks = 0; ks < 4; ks++) {
            unsigned aa[8];
            int rbase = (32 * w + g) * 36 + 8 * ks + t;
            aa[0] = Ab[rbase];
            aa[1] = Ab[rbase + 8 * 36];
            aa[2] = Ab[rbase + 4];
            aa[3] = Ab[rbase + 8 * 36 + 4];
            aa[4] = Ab[rbase + 16 * 36];
            aa[5] = Ab[rbase + 24 * 36];
            aa[6] = Ab[rbase + 16 * 36 + 4];
            aa[7] = Ab[rbase + 24 * 36 + 4];
#pragma unroll
            for (int j = 0; j < 8; j++) {
                unsigned b0 = Wb[(8 * j + g) * 36 + 8 * ks + t];
                unsigned b1 = Wb[(8 * j + g) * 36 + 8 * ks + t + 4];
                mma8(cf[0][j], aa, b0, b1);
                mma8(cf[1][j], aa + 4, b0, b1);
            }
        }
    }
}

// Fused Q/K/V projection: blockIdx.z selects weight/bias/destination.
__global__ __launch_bounds__(128, 4) void proj_qkv_kernel(
    const float* __restrict__ bq, const float* __restrict__ bk,
    const float* __restrict__ bv)
{
    int which = blockIdx.z;
    const unsigned* W  = g_wt + which * 65536;
    const float* bias  = (which == 0) ? bq : (which == 1) ? bk : bv;
    unsigned* dst      = (which == 0) ? g_q : (which == 1) ? g_k : g_v;
    float sc           = (which == 0) ? QSL2E : 1.0f;

    float4 cf[2][8];
    int m0 = blockIdx.y * 128, n0 = blockIdx.x * 64;
    gemm_mma_core(g_xt, W, m0, n0, cf);

    int tid = threadIdx.x;
    int w = tid >> 5, lane = tid & 31;
    int g = lane >> 2, t = lane & 3;

#pragma unroll
    for (int f = 0; f < 2; f++) {
        int m_a = m0 + 32 * w + g + 16 * f;
        int m_b = m_a + 8;
#pragma unroll
        for (int j = 0; j < 8; j++) {
            int c = n0 + 8 * j + 2 * t;          // even, c&31 <= 30
            int h = c >> 5, d = c & 31;
            float b0 = __ldg(bias + c), b1 = __ldg(bias + c + 1);
            {
                int b = m_a >> 10, n = m_a & 1023;
                unsigned* p = dst + (((size_t)(b * HEADS + h)) * NSEQ + n) * DKDIM + d;
                p[0] = f2tf((cf[f][j].x + b0) * sc);
                p[1] = f2tf((cf[f][j].y + b1) * sc);
            }
            {
                int b = m_b >> 10, n = m_b & 1023;
                unsigned* p = dst + (((size_t)(b * HEADS + h)) * NSEQ + n) * DKDIM + d;
                p[0] = f2tf((cf[f][j].z + b0) * sc);
                p[1] = f2tf((cf[f][j].w + b1) * sc);
            }
        }
    }
}

__global__ __launch_bounds__(128, 4) void out_proj_kernel(
    const float* __restrict__ bias, float* __restrict__ C)
{
    float4 cf[2][8];
    int m0 = blockIdx.y * 128, n0 = blockIdx.x * 64;
    gemm_mma_core(g_o, g_wt + 3 * 65536, m0, n0, cf);

    int tid = threadIdx.x;
    int w = tid >> 5, lane = tid & 31;
    int g = lane >> 2, t = lane & 3;
#pragma unroll
    for (int f = 0; f < 2; f++) {
        int m_a = m0 + 32 * w + g + 16 * f;
#pragma unroll
        for (int j = 0; j < 8; j++) {
            int c = n0 + 8 * j + 2 * t;
            float b0 = __ldg(bias + c), b1 = __ldg(bias + c + 1);
            *(float2*)(C + (size_t)m_a * DMODEL + c) =
                make_float2(cf[f][j].x + b0, cf[f][j].y + b1);
            *(float2*)(C + (size_t)(m_a + 8) * DMODEL + c) =
                make_float2(cf[f][j].z + b0, cf[f][j].w + b1);
        }
    }
}

// ---------------------------------------------------------------------------
// Fused flash attention (log2-domain softmax), tf32 mma, arithmetic rel bias.
// Block: 128 threads (4 warps), 128 query rows; warp w owns rows 32w..32w+31.
// __launch_bounds__(128,3): cap regs at 168 so 3 CTAs/SM fit (smem 73.7KB
// already permits 3). 16 key tiles of 64, cp.async double-buffered.
// SMEM (words): K0 K1 V0 V1 Ps. Strides: K 36, V 40, P 68 (bank-audited).
// ---------------------------------------------------------------------------
#define AT_KW (64 * 36)
#define AT_VW (64 * 40)
#define AT_PS (128 * 68)
#define ATTN_SMEM_WORDS (2 * AT_KW + 2 * AT_VW + AT_PS)   // 18432 w = 73728 B

__global__ __launch_bounds__(128, 3) void attn_kernel(
    const float* __restrict__ bias_table)
{
    extern __shared__ unsigned sm[];
    unsigned sb = (unsigned)__cvta_generic_to_shared(sm);
    unsigned* Ps = sm + 2 * AT_KW + 2 * AT_VW;

    int bh = blockIdx.y;                 // 0..127
    int h = bh & (HEADS - 1);
    int b = bh >> 3;
    int qbase = blockIdx.x * 128;
    int tid = threadIdx.x;
    int w = tid >> 5, lane = tid & 31;
    int g = lane >> 2, t = lane & 3;

    const unsigned* qptr = g_q + (size_t)bh * NSEQ * DKDIM;
    const unsigned* kptr = g_k + (size_t)bh * NSEQ * DKDIM;
    const unsigned* vptr = g_v + (size_t)bh * NSEQ * DKDIM;
    const float* brow = bias_table + h * NUMREL;

    int r0 = qbase + 32 * w + g;   // warp's first fragment row
    int rr = tid >> 3;             // 0..15
    int cc = (tid & 7) << 2;       // 0,4,...,28

    auto copy_kv = [&](int kb, int buf) {
        unsigned ksm = sb + buf * (AT_KW * 4);
        unsigned vsm = sb + (2 * AT_KW + buf * AT_VW) * 4;
#pragma unroll
        for (int i = 0; i < 4; i++) {
            int row = 16 * i + rr;
            cp16(ksm + (row * 36 + cc) * 4,
                 kptr + (size_t)(kb + row) * DKDIM + cc);
            cp16(vsm + (row * 40 + cc) * 4,
                 vptr + (size_t)(kb + row) * DKDIM + cc);
        }
        cp_commit();
    };

    // --- Q fragments (persist): frag f covers rows r0+16f, r0+16f+8 ---
    unsigned qa[4][8];
#pragma unroll
    for (int f = 0; f < 2; f++) {
        const unsigned* qA = qptr + (size_t)(r0 + 16 * f) * DKDIM;
        const unsigned* qB = qA + 8 * DKDIM;
#pragma unroll
        for (int ks = 0; ks < 4; ks++) {
            qa[ks][4 * f + 0] = __ldg(qA + 8 * ks + t);
            qa[ks][4 * f + 1] = __ldg(qB + 8 * ks + t);
            qa[ks][4 * f + 2] = __ldg(qA + 8 * ks + t + 4);
            qa[ks][4 * f + 3] = __ldg(qB + 8 * ks + t + 4);
        }
    }

    // rowcodes for arithmetic rel-index (rows r0, r0+8, r0+16, r0+24)
    int rc[4];
#pragma unroll
    for (int i = 0; i < 4; i++) {
        int qr = r0 + 8 * i;
        rc[i] = (qr >> 5) * 63 + (qr & 31) + 1984;
    }
    int cc0[8];
#pragma unroll
    for (int j = 0; j < 8; j++) {
        int x = 8 * j + 2 * t;
        cc0[j] = (x >> 5) * 63 + (x & 31);
    }

    float m[4], l[4];
    float4 of[2][4];
#pragma unroll
    for (int i = 0; i < 4; i++) { m[i] = -1e30f; l[i] = 0.f; }
#pragma unroll
    for (int f = 0; f < 2; f++)
#pragma unroll
        for (int jj = 0; jj < 4; jj++) of[f][jj] = make_float4(0.f, 0.f, 0.f, 0.f);

    copy_kv(0, 0);

    for (int s = 0; s < 16; s++) {        // 16 key tiles = NSEQ/64
        int kb = 64 * s;
        cp_wait0();
        __syncthreads();
        if (s < 15) copy_kv(kb + 64, (s + 1) & 1);

        const unsigned* Kb = sm + (s & 1) * AT_KW;
        const unsigned* Vb = sm + 2 * AT_KW + (s & 1) * AT_VW;

        // ---- S = Q K^T : 8 n-tiles x 4 k-steps, 2 M-frags per B load ----
        float4 sf[2][8];
#pragma unroll
        for (int f = 0; f < 2; f++)
#pragma unroll
            for (int j = 0; j < 8; j++) sf[f][j] = make_float4(0.f, 0.f, 0.f, 0.f);
#pragma unroll
        for (int ks = 0; ks < 4; ks++) {
#pragma unroll
            for (int j = 0; j < 8; j++) {
                unsigned b0 = Kb[(8 * j + g) * 36 + 8 * ks + t];
                unsigned b1 = Kb[(8 * j + g) * 36 + 8 * ks + t + 4];
                mma8(sf[0][j], &qa[ks][0], b0, b1);
                mma8(sf[1][j], &qa[ks][4], b0, b1);
            }
        }

        // ---- bias + online softmax (log2 domain) ----
        int koff = (kb >> 5) * 63;
        int base0 = rc[0] - koff, base1 = rc[1] - koff;
        int base2 = rc[2] - koff, base3 = rc[3] - koff;

        float mx[4] = {-1e30f, -1e30f, -1e30f, -1e30f};
#pragma unroll
        for (int j = 0; j < 8; j++) {
            int iA0 = base0 - cc0[j];
            int iA1 = base1 - cc0[j];
            int iA2 = base2 - cc0[j];
            int iA3 = base3 - cc0[j];
            sf[0][j].x = fmaf(__ldg(brow + iA0),     LOG2E, sf[0][j].x);
            sf[0][j].y = fmaf(__ldg(brow + iA0 - 1), LOG2E, sf[0][j].y);
            sf[0][j].z = fmaf(__ldg(brow + iA1),     LOG2E, sf[0][j].z);
            sf[0][j].w = fmaf(__ldg(brow + iA1 - 1), LOG2E, sf[0][j].w);
            sf[1][j].x = fmaf(__ldg(brow + iA2),     LOG2E, sf[1][j].x);
            sf[1][j].y = fmaf(__ldg(brow + iA2 - 1), LOG2E, sf[1][j].y);
            sf[1][j].z = fmaf(__ldg(brow + iA3),     LOG2E, sf[1][j].z);
            sf[1][j].w = fmaf(__ldg(brow + iA3 - 1), LOG2E, sf[1][j].w);
            mx[0] = fmaxf(mx[0], fmaxf(sf[0][j].x, sf[0][j].y));
            mx[1] = fmaxf(mx[1], fmaxf(sf[0][j].z, sf[0][j].w));
            mx[2] = fmaxf(mx[2], fmaxf(sf[1][j].x, sf[1][j].y));
            mx[3] = fmaxf(mx[3], fmaxf(sf[1][j].z, sf[1][j].w));
        }
        float fac[4], s4[4];
#pragma unroll
        for (int i = 0; i < 4; i++) {
            mx[i] = fmaxf(mx[i], __shfl_xor_sync(0xffffffffu, mx[i], 1));
            mx[i] = fmaxf(mx[i], __shfl_xor_sync(0xffffffffu, mx[i], 2));
            float nm = fmaxf(m[i], mx[i]);
            fac[i] = ex2(m[i] - nm);
            m[i] = nm;
            s4[i] = 0.f;
        }
#pragma unroll
        for (int f = 0; f < 2; f++) {
#pragma unroll
            for (int j = 0; j < 8; j++) {
                sf[f][j].x = ex2(sf[f][j].x - m[2 * f]);
                sf[f][j].y = ex2(sf[f][j].y - m[2 * f]);
                sf[f][j].z = ex2(sf[f][j].z - m[2 * f + 1]);
                sf[f][j].w = ex2(sf[f][j].w - m[2 * f + 1]);
                s4[2 * f]     += sf[f][j].x + sf[f][j].y;
                s4[2 * f + 1] += sf[f][j].z + sf[f][j].w;
                uint2 p0; p0.x = f2tf(sf[f][j].x); p0.y = f2tf(sf[f][j].y);
                uint2 p1; p1.x = f2tf(sf[f][j].z); p1.y = f2tf(sf[f][j].w);
                *(uint2*)&Ps[(32 * w + g + 16 * f) * 68 + 8 * j + 2 * t] = p0;
                *(uint2*)&Ps[(32 * w + g + 16 * f + 8) * 68 + 8 * j + 2 * t] = p1;
            }
        }
#pragma unroll
        for (int i = 0; i < 4; i++) {
            s4[i] += __shfl_xor_sync(0xffffffffu, s4[i], 1);
            s4[i] += __shfl_xor_sync(0xffffffffu, s4[i], 2);
            l[i] = l[i] * fac[i] + s4[i];
        }
#pragma unroll
        for (int f = 0; f < 2; f++)
#pragma unroll
            for (int jj = 0; jj < 4; jj++) {
                of[f][jj].x *= fac[2 * f];     of[f][jj].y *= fac[2 * f];
                of[f][jj].z *= fac[2 * f + 1]; of[f][jj].w *= fac[2 * f + 1];
            }
        __syncwarp();   // warp's own P rows visible

        // ---- O += P @ V : 4 n-tiles x 8 k-steps, 2 M-frags per B load ----
#pragma unroll
        for (int ks = 0; ks < 8; ks++) {
            unsigned pa[8];
            int pbase = (32 * w + g) * 68 + 8 * ks + t;
            pa[0] = Ps[pbase];
            pa[1] = Ps[pbase + 8 * 68];
            pa[2] = Ps[pbase + 4];
            pa[3] = Ps[pbase + 8 * 68 + 4];
            pa[4] = Ps[pbase + 16 * 68];
            pa[5] = Ps[pbase + 24 * 68];
            pa[6] = Ps[pbase + 16 * 68 + 4];
            pa[7] = Ps[pbase + 24 * 68 + 4];
#pragma unroll
            for (int jj = 0; jj < 4; jj++) {
                unsigned b0 = Vb[(8 * ks + t) * 40 + 8 * jj + g];
                unsigned b1 = Vb[(8 * ks + t + 4) * 40 + 8 * jj + g];
                mma8(of[0][jj], pa, b0, b1);
                mma8(of[1][jj], pa + 4, b0, b1);
            }
        }
    }

    // ---- normalize + write O as tf32 bits in [B, N, H*dk] layout ----
#pragma unroll
    for (int f = 0; f < 2; f++) {
        float inv0 = 1.0f / l[2 * f], inv1 = 1.0f / l[2 * f + 1];
        int qrA = r0 + 16 * f, qrB = qrA + 8;
#pragma unroll
        for (int jj = 0; jj < 4; jj++) {
            int col = h * DKDIM + 8 * jj + 2 * t;
            uint2 u0, u1;
            u0.x = f2tf(of[f][jj].x * inv0); u0.y = f2tf(of[f][jj].y * inv0);
            u1.x = f2tf(of[f][jj].z * inv1); u1.y = f2tf(of[f][jj].w * inv1);
            *(uint2*)(g_o + ((size_t)b * NSEQ + qrA) * DMODEL + col) = u0;
            *(uint2*)(g_o + ((size_t)b * NSEQ + qrB) * DMODEL + col) = u1;
        }
    }
}

// ---------------------------------------------------------------------------
extern "C" void kernel_launch(void* const* d_in, const int* in_sizes, int n_in,
                              void* d_out, int out_size)
{
    const float* x          = (const float*)d_in[0];
    const float* Wq         = (const float*)d_in[1];
    const float* bq         = (const float*)d_in[2];
    const float* Wk         = (const float*)d_in[3];
    const float* bk         = (const float*)d_in[4];
    const float* Wv         = (const float*)d_in[5];
    const float* bv         = (const float*)d_in[6];
    const float* Wo         = (const float*)d_in[7];
    const float* bo         = (const float*)d_in[8];
    const float* bias_table = (const float*)d_in[9];
    float* out = (float*)d_out;

    cudaFuncSetAttribute(attn_kernel,
                         cudaFuncAttributeMaxDynamicSharedMemorySize,
                         ATTN_SMEM_WORDS * 4);
    cudaFuncSetAttribute(proj_qkv_kernel,
                         cudaFuncAttributeMaxDynamicSharedMemorySize,
                         GEMM_SMEM_WORDS * 4);
    cudaFuncSetAttribute(out_proj_kernel,
                         cudaFuncAttributeMaxDynamicSharedMemorySize,
                         GEMM_SMEM_WORDS * 4);

    prep_kernel<<<1024, 256>>>(x, Wq, Wk, Wv, Wo);

    dim3 pgrid(DMODEL / 64, (BATCH * NSEQ) / 128, 3);   // (4, 128, 3)
    proj_qkv_kernel<<<pgrid, 128, GEMM_SMEM_WORDS * 4>>>(bq, bk, bv);

    attn_kernel<<<dim3(NSEQ / 128, BATCH * HEADS), 128,
                  ATTN_SMEM_WORDS * 4>>>(bias_table);

    dim3 ogrid(DMODEL / 64, (BATCH * NSEQ) / 128);      // (4, 128)
    out_proj_kernel<<<ogrid, 128, GEMM_SMEM_WORDS * 4>>>(bo, out);
}